// round 13
// speedup vs baseline: 11.6577x; 1.0257x over previous
#include <cuda_runtime.h>
#include <cuda.h>
#include <cuda_bf16.h>
#include <math.h>
#include <stdint.h>

#define Bq 32
#define Sq 196
#define Dq 768
#define Hq 12
#define Eq 8
#define Fq 3072
#define DHq 64
#define NTOK (Bq*Sq)
#define MPAD 6400

#define HAS_TCGEN05 (defined(__CUDA_ARCH_FEAT_SM103_ALL) || defined(__CUDA_ARCH_FEAT_SM100_ALL))

// ---------------- scratch ------------------------------------------------------
__device__ __align__(256) float d_qkvh[3*NTOK*Dq];
__device__ __align__(256) float d_tmp[NTOK*Dq];
__device__ __align__(256) float d_x  [NTOK*Dq];
__device__ __align__(256) float d_y  [Eq*MPAD*Dq];
__device__ __align__(256) float d_gates[MPAD*Eq];

__device__ __align__(256) __nv_bfloat16 d_inhi[NTOK*Dq];
__device__ __align__(256) __nv_bfloat16 d_inlo[NTOK*Dq];
__device__ __align__(256) __nv_bfloat16 d_xhi[MPAD*Dq];
__device__ __align__(256) __nv_bfloat16 d_hhi[Eq*MPAD*Fq];  // h; also qkv-hi staging early
__device__ __align__(256) __nv_bfloat16 d_qlo[3*NTOK*Dq];   // qkv-lo staging
__device__ __align__(256) __nv_bfloat16 d_w1t_hi[Eq*Fq*Dq];
__device__ __align__(256) __nv_bfloat16 d_w2t_hi[Eq*Dq*Fq];
__device__ __align__(256) __nv_bfloat16 d_wqkvt_hi[3*Dq*Dq];
__device__ __align__(256) __nv_bfloat16 d_wqkvt_lo[3*Dq*Dq];
__device__ __align__(256) __nv_bfloat16 d_wot_hi[Dq*Dq];
__device__ __align__(256) __nv_bfloat16 d_wot_lo[Dq*Dq];

// ---------------- PTX helpers ---------------------------------------------------
__device__ __forceinline__ uint32_t smem_u32(const void* p) {
    uint32_t a;
    asm("{ .reg .u64 t; cvta.to.shared.u64 t, %1; cvt.u32.u64 %0, t; }" : "=r"(a) : "l"(p));
    return a;
}

#if HAS_TCGEN05
__device__ __forceinline__ bool elect_one() {
    uint32_t p;
    asm volatile("{\n .reg .pred p;\n elect.sync _|p, 0xFFFFFFFF;\n selp.b32 %0,1,0,p;\n}" : "=r"(p));
    return p != 0;
}
#define MBARRIER_INIT(addr, cnt) \
    asm volatile("mbarrier.init.shared.b64 [%0], %1;" :: "r"((uint32_t)(addr)), "r"((uint32_t)(cnt)) : "memory")
#define MBARRIER_INVAL(addr) \
    asm volatile("mbarrier.inval.shared.b64 [%0];" :: "r"((uint32_t)(addr)) : "memory")
#define MBARRIER_EXPECT_TX(addr, tx) \
    asm volatile("mbarrier.arrive.expect_tx.shared.b64 _, [%0], %1;" \
        :: "r"((uint32_t)(addr)), "r"((uint32_t)(tx)) : "memory")
#define MBARRIER_WAIT_PARITY(mbar, par) do { \
    uint32_t _m = (uint32_t)(mbar), _p = (uint32_t)(par), _d; \
    asm volatile("{\n\t.reg .pred p;\n\t" \
        "mbarrier.try_wait.parity.acquire.cta.shared::cta.b64 p, [%1], %2;\n\t" \
        "selp.b32 %0, 1, 0, p;\n\t}" : "=r"(_d) : "r"(_m), "r"(_p) : "memory"); \
    if (!_d) { \
        asm volatile("{\n\t.reg .pred P1;\n\t" \
            "WL_%=:\n\t" \
            "mbarrier.try_wait.parity.acquire.cta.shared::cta.b64 P1, [%0], %1, 0x989680;\n\t" \
            "@P1 bra.uni WD_%=;\n\tbra.uni WL_%=;\n\tWD_%=:\n\t}" \
            :: "r"(_m), "r"(_p) : "memory"); \
    } \
} while(0)
#define TCGEN05_ALLOC(a, n) \
    asm volatile("tcgen05.alloc.cta_group::1.sync.aligned.shared::cta.b32 [%0], %1;" \
        :: "r"((uint32_t)(a)), "r"((uint32_t)(n)) : "memory")
#define TCGEN05_DEALLOC(t, n) \
    asm volatile("tcgen05.dealloc.cta_group::1.sync.aligned.b32 %0, %1;" :: "r"(t), "r"(n))
#define TCGEN05_RELINQ() \
    asm volatile("tcgen05.relinquish_alloc_permit.cta_group::1.sync.aligned;")
#define TCGEN05_COMMIT(m) \
    asm volatile("tcgen05.commit.cta_group::1.mbarrier::arrive::one.shared::cluster.b64 [%0];" \
        :: "r"((uint32_t)(m)) : "memory")
#define TCGEN05_FENCE_AFTER()  asm volatile("tcgen05.fence::after_thread_sync;" ::: "memory")
#define TCGEN05_FENCE_BEFORE() asm volatile("tcgen05.fence::before_thread_sync;" ::: "memory")
#define TCGEN05_WAIT_LD() asm volatile("tcgen05.wait::ld.sync.aligned;" ::: "memory")
#define FENCE_ASYNC_SHARED() asm volatile("fence.proxy.async.shared::cta;" ::: "memory")
#define CP_ASYNC16(dst, src) \
    asm volatile("cp.async.cg.shared.global [%0], [%1], 16;" :: "r"((uint32_t)(dst)), "l"(src))
#define CP_COMMIT() asm volatile("cp.async.commit_group;" ::: "memory")
#define CP_WAIT(n)  asm volatile("cp.async.wait_group %0;" :: "n"(n) : "memory")
#define TMA_LOAD_3D(sm, map, cx, cy, cz, mb) \
    asm volatile("cp.async.bulk.tensor.3d.shared::cta.global.tile.mbarrier::complete_tx::bytes " \
        "[%0], [%1, {%2, %3, %4}], [%5];" \
        :: "r"((uint32_t)(sm)), "l"(map), "r"((int32_t)(cx)), "r"((int32_t)(cy)), \
           "r"((int32_t)(cz)), "r"((uint32_t)(mb)) : "memory")
#define TCGEN05_LD_32X32B_X32(r, ta) \
    asm volatile("tcgen05.ld.sync.aligned.32x32b.x32.b32 " \
        "{%0, %1, %2, %3, %4, %5, %6, %7, %8, %9, %10, %11, %12, %13, %14, %15, " \
        " %16, %17, %18, %19, %20, %21, %22, %23, %24, %25, %26, %27, %28, %29, %30, %31}, [%32];" \
        : "=r"((r)[0]), "=r"((r)[1]), "=r"((r)[2]), "=r"((r)[3]), "=r"((r)[4]), "=r"((r)[5]), \
          "=r"((r)[6]), "=r"((r)[7]), "=r"((r)[8]), "=r"((r)[9]), "=r"((r)[10]), "=r"((r)[11]), \
          "=r"((r)[12]), "=r"((r)[13]), "=r"((r)[14]), "=r"((r)[15]), "=r"((r)[16]), "=r"((r)[17]), \
          "=r"((r)[18]), "=r"((r)[19]), "=r"((r)[20]), "=r"((r)[21]), "=r"((r)[22]), "=r"((r)[23]), \
          "=r"((r)[24]), "=r"((r)[25]), "=r"((r)[26]), "=r"((r)[27]), "=r"((r)[28]), "=r"((r)[29]), \
          "=r"((r)[30]), "=r"((r)[31]) : "r"(ta))

static constexpr uint64_t DESC_SW128 =
    (uint64_t(2) << 61) | (uint64_t(1) << 46) | (uint64_t(64) << 32) | (uint64_t(1) << 16);
static constexpr uint64_t DESC_SW64 =
    (uint64_t(4) << 61) | (uint64_t(1) << 46) | (uint64_t(32) << 32) | (uint64_t(1) << 16);
#define MKD128(a) (DESC_SW128 | ((uint64_t)((a) >> 4) & 0x3FFF))
#define MKD64(a)  (DESC_SW64  | ((uint64_t)((a) >> 4) & 0x3FFF))

__device__ __forceinline__ void mma_bf16_ss(uint32_t d, uint64_t ad, uint64_t bd,
                                            uint32_t idesc, uint32_t en) {
    asm volatile(
        "{\n\t.reg .pred p;\n\tsetp.ne.u32 p, %5, 0;\n\t"
        "tcgen05.mma.cta_group::1.kind::f16 [%0], %1, %2, %3, {%4,%4,%4,%4}, p;\n\t}"
        :: "r"(d), "l"(ad), "l"(bd), "r"(idesc), "r"(0u), "r"(en) : "memory");
}
static constexpr uint32_t IDESC_BF16 =
    (1u << 4) | (1u << 7) | (1u << 10) | ((256 / 8) << 17) | ((128 / 16) << 24);
#endif

// ======================= TM128 tc GEMM (QKV batched / O-proj, 3-term) ===========
#define TM 128
#define TN 256
#define TK 64
#define STAGE_BYTES 98304
#define SM_DATA 1024
#define TC_SMEM (SM_DATA + 2*STAGE_BYTES)

#if HAS_TCGEN05
__device__ __forceinline__ void load_slab128(
    uint32_t sbase, int stage,
    const __nv_bfloat16* __restrict__ Ahi, const __nv_bfloat16* __restrict__ Alo,
    const __nv_bfloat16* __restrict__ Bhi, const __nv_bfloat16* __restrict__ Blo,
    int m0, int n0, int k0, int K)
{
    const int tid = threadIdx.x;
    const uint32_t base = sbase + SM_DATA + stage * STAGE_BYTES;
#pragma unroll
    for (int i = 0; i < 4; i++) {
        int idx = i * 256 + tid;
        int row = idx >> 3, c4 = idx & 7;
        int off = row * 128 + c4 * 16;
        int sw  = off ^ ((off >> 3) & 0x70);
        size_t g = (size_t)(m0 + row) * K + k0 + c4 * 8;
        CP_ASYNC16(base + sw, Ahi + g);
        CP_ASYNC16(base + 16384 + sw, Alo + g);
    }
#pragma unroll
    for (int i = 0; i < 8; i++) {
        int idx = i * 256 + tid;
        int row = idx >> 3, c4 = idx & 7;
        int off = row * 128 + c4 * 16;
        int sw  = off ^ ((off >> 3) & 0x70);
        size_t g = (size_t)(n0 + row) * K + k0 + c4 * 8;
        CP_ASYNC16(base + 32768 + sw, Bhi + g);
        CP_ASYNC16(base + 65536 + sw, Blo + g);
    }
    CP_COMMIT();
}
#endif

template<int MODE>   // 2: z-batched C=AW+b(z)   3: C=AW+b+res
__global__ void __launch_bounds__(256)
tc_gemm(const __nv_bfloat16* __restrict__ Ahi, const __nv_bfloat16* __restrict__ Alo,
        const __nv_bfloat16* __restrict__ Bhi, const __nv_bfloat16* __restrict__ Blo,
        const float* __restrict__ b0, const float* __restrict__ b1,
        const float* __restrict__ b2, const float* __restrict__ res,
        float* __restrict__ Cf, int M, int N, int K,
        size_t sA, size_t sB, size_t sC)
{
    extern __shared__ __align__(1024) char smx[];
    const int z = blockIdx.z;
    Ahi += z * sA; Alo += z * sA;
    Bhi += z * sB; Blo += z * sB;
    Cf  += z * sC;
    const float* bias = (z == 0) ? b0 : (z == 1) ? b1 : b2;
#if HAS_TCGEN05
    const uint32_t sb = smem_u32(smx);
    const int tid = threadIdx.x;
    const int wid = tid >> 5, lane = tid & 31;
    const int m0 = blockIdx.y * TM, n0 = blockIdx.x * TN;

    if (wid == 0) { TCGEN05_ALLOC(sb, 256); TCGEN05_RELINQ(); }
    if (tid == 0) { MBARRIER_INIT(sb + 8, 1); MBARRIER_INIT(sb + 16, 1); }
    __syncthreads();
    uint32_t tmem;
    asm volatile("ld.shared.b32 %0, [%1];" : "=r"(tmem) : "r"(sb));

    const int NS = K / TK;
    load_slab128(sb, 0, Ahi, Alo, Bhi, Blo, m0, n0, 0, K);
    int ph0 = 0, ph1 = 0;
    for (int s = 0; s < NS; s++) {
        const int buf = s & 1;
        if (s + 1 < NS) {
            const int nb = 1 - buf;
            if (s >= 1) {
                if (nb == 0) { MBARRIER_WAIT_PARITY(sb + 8,  ph0); ph0 ^= 1; }
                else         { MBARRIER_WAIT_PARITY(sb + 16, ph1); ph1 ^= 1; }
            }
            load_slab128(sb, nb, Ahi, Alo, Bhi, Blo, m0, n0, (s + 1) * TK, K);
            CP_WAIT(1);
        } else {
            CP_WAIT(0);
        }
        FENCE_ASYNC_SHARED();
        __syncthreads();
        if (wid == 0) {
            TCGEN05_FENCE_AFTER();
            if (elect_one()) {
                const uint32_t tb = sb + SM_DATA + buf * STAGE_BYTES;
                const uint64_t ah = MKD128(tb), al = MKD128(tb + 16384);
                const uint64_t bh = MKD128(tb + 32768), bl = MKD128(tb + 65536);
#pragma unroll
                for (int ks = 0; ks < 4; ks++) {
                    const uint32_t en0 = (s == 0 && ks == 0) ? 0u : 1u;
                    mma_bf16_ss(tmem, ah + ks * 2, bh + ks * 2, IDESC_BF16, en0);
                    mma_bf16_ss(tmem, ah + ks * 2, bl + ks * 2, IDESC_BF16, 1u);
                    mma_bf16_ss(tmem, al + ks * 2, bh + ks * 2, IDESC_BF16, 1u);
                }
                TCGEN05_COMMIT(sb + 8 + buf * 8);
            }
        }
    }
    if (((NS - 1) & 1) == 0) { MBARRIER_WAIT_PARITY(sb + 8,  ph0); }
    else                     { MBARRIER_WAIT_PARITY(sb + 16, ph1); }
    TCGEN05_FENCE_AFTER();

    const int sub = wid & 3, cg = wid >> 2;
    const int row = m0 + sub * 32 + lane;
#pragma unroll
    for (int ch = 0; ch < 4; ch++) {
        const int colb = cg * 128 + ch * 32;
        uint32_t r[32];
        TCGEN05_LD_32X32B_X32(r, tmem + colb);
        TCGEN05_WAIT_LD();
        const size_t base = (size_t)row * N + n0 + colb;
        const float4* bv = (const float4*)(bias + n0 + colb);
        float4* dst = (float4*)(Cf + base);
        const float4* rv = (MODE == 3) ? (const float4*)(res + base) : nullptr;
#pragma unroll
        for (int i = 0; i < 8; i++) {
            float4 b4 = bv[i];
            float4 o;
            o.x = __uint_as_float(r[i*4+0]) + b4.x;
            o.y = __uint_as_float(r[i*4+1]) + b4.y;
            o.z = __uint_as_float(r[i*4+2]) + b4.z;
            o.w = __uint_as_float(r[i*4+3]) + b4.w;
            if (MODE == 3) { float4 t = rv[i]; o.x += t.x; o.y += t.y; o.z += t.z; o.w += t.w; }
            dst[i] = o;
        }
    }
    TCGEN05_FENCE_BEFORE();
    __syncthreads();
    if (tid == 0) { MBARRIER_INVAL(sb + 8); MBARRIER_INVAL(sb + 16); }
    __syncthreads();
    if (wid == 0) TCGEN05_DEALLOC(tmem, 256);
#else
    float* As = (float*)smx;
    float* Bs = As + 16 * 128;
    const int tid = threadIdx.x;
    const int m0 = blockIdx.y * TM, n0x = blockIdx.x * TN;
    const int tx = tid & 15, ty = tid >> 4;
    const int mr = ty * 8, nr = tx * 8;
    for (int half = 0; half < 2; half++) {
        const int n0 = n0x + half * 128;
        float acc[8][8];
#pragma unroll
        for (int i = 0; i < 8; i++)
#pragma unroll
            for (int j = 0; j < 8; j++) acc[i][j] = 0.f;
        for (int k0 = 0; k0 < K; k0 += 16) {
            __syncthreads();
#pragma unroll
            for (int i = 0; i < 8; i++) {
                int idx = i * 256 + tid;
                int kk = idx >> 7, mm = idx & 127;
                size_t ga = (size_t)(m0 + mm) * K + k0 + kk;
                size_t gb = (size_t)(n0 + mm) * K + k0 + kk;
                As[kk*128+mm] = __bfloat162float(Ahi[ga]) + __bfloat162float(Alo[ga]);
                Bs[kk*128+mm] = __bfloat162float(Bhi[gb]) + __bfloat162float(Blo[gb]);
            }
            __syncthreads();
#pragma unroll
            for (int kk = 0; kk < 16; kk++) {
                float a0[8], b0r[8];
#pragma unroll
                for (int i = 0; i < 8; i++) a0[i] = As[kk*128+mr+i];
#pragma unroll
                for (int j = 0; j < 8; j++) b0r[j] = Bs[kk*128+nr+j];
#pragma unroll
                for (int i = 0; i < 8; i++)
#pragma unroll
                    for (int j = 0; j < 8; j++)
                        acc[i][j] = fmaf(a0[i], b0r[j], acc[i][j]);
            }
        }
#pragma unroll
        for (int i = 0; i < 8; i++) {
            const int row = m0 + mr + i;
#pragma unroll
            for (int j = 0; j < 8; j++) {
                const int col = n0 + nr + j;
                const size_t idx = (size_t)row * N + col;
                float v = acc[i][j] + bias[col];
                if (MODE == 2) Cf[idx] = v; else Cf[idx] = v + res[idx];
            }
        }
    }
#endif
}

// ======================= MoE GEMM: pure bf16, TMA producer/consumer =============
#define T2K 32
#define SLAB2 32768
#define TC2_SMEM (1024 + 6*SLAB2)   // 197632

template<int MODE>   // 0: gelu(acc+bias)->bf16   1: Cf = acc + bias
__global__ void __launch_bounds__(256)
tc_gemm2(const __grid_constant__ CUtensorMap mA, const __grid_constant__ CUtensorMap mB,
         const float* __restrict__ bias, float* __restrict__ Cf,
         __nv_bfloat16* __restrict__ Chi,
         int N, int K, size_t sBias, size_t sC,
         const __nv_bfloat16* __restrict__ A, const __nv_bfloat16* __restrict__ B,
         size_t sA, size_t sB)
{
    extern __shared__ __align__(1024) char smx[];
    const int z = blockIdx.z;
    bias += z * sBias;
#if HAS_TCGEN05
    const uint32_t sb = smem_u32(smx);
    const int tid = threadIdx.x;
    const int wid = tid >> 5, lane = tid & 31;
    const int m0 = blockIdx.y * 256, n0 = blockIdx.x * 256;
    const int za = (MODE == 0) ? 0 : z;

    if (wid == 0) { TCGEN05_ALLOC(sb, 512); TCGEN05_RELINQ(); }
    if (tid == 0) {
#pragma unroll
        for (int i = 0; i < 6; i++) { MBARRIER_INIT(sb + 8 + i * 8, 1); MBARRIER_INIT(sb + 56 + i * 8, 1); }
        MBARRIER_INIT(sb + 104, 1);
        FENCE_ASYNC_SHARED();
    }
    __syncthreads();
    uint32_t tmem;
    asm volatile("ld.shared.b32 %0, [%1];" : "=r"(tmem) : "r"(sb));

    const int NS = K / T2K;
    if (wid == 1) {
        if (elect_one()) {
            for (int s = 0; s < NS; s++) {
                const int st = s % 6;
                if (s >= 6) MBARRIER_WAIT_PARITY(sb + 56 + st * 8, ((s / 6) - 1) & 1);
                MBARRIER_EXPECT_TX(sb + 8 + st * 8, (uint32_t)SLAB2);
                const uint32_t stb = sb + 1024 + st * SLAB2;
                const int k0 = s * T2K;
                TMA_LOAD_3D(stb,         &mA, k0, m0, za, sb + 8 + st * 8);
                TMA_LOAD_3D(stb + 16384, &mB, k0, n0, z,  sb + 8 + st * 8);
            }
        }
    } else if (wid == 0) {
        TCGEN05_FENCE_AFTER();
        if (elect_one()) {
            for (int s = 0; s < NS; s++) {
                const int st = s % 6;
                MBARRIER_WAIT_PARITY(sb + 8 + st * 8, (s / 6) & 1);
                const uint32_t tb = sb + 1024 + st * SLAB2;
                const uint64_t a0 = MKD64(tb);
                const uint64_t a1 = a0 + 512;
                const uint64_t bh = MKD64(tb + 16384);
#pragma unroll
                for (int ks = 0; ks < 2; ks++) {
                    const uint32_t en0 = (s == 0 && ks == 0) ? 0u : 1u;
                    mma_bf16_ss(tmem,       a0 + ks * 2, bh + ks * 2, IDESC_BF16, en0);
                    mma_bf16_ss(tmem + 256, a1 + ks * 2, bh + ks * 2, IDESC_BF16, en0);
                }
                TCGEN05_COMMIT(sb + 56 + st * 8);
            }
            TCGEN05_COMMIT(sb + 104);
        }
    }

    MBARRIER_WAIT_PARITY(sb + 104, 0);
    TCGEN05_FENCE_AFTER();

    const int accSel = wid >> 2, sub = wid & 3;
    const int row = m0 + accSel * 128 + sub * 32 + lane;
    const uint32_t tacc = tmem + accSel * 256;
    if (MODE == 0) Chi += z * sC;
    else           Cf  += z * sC;
#pragma unroll
    for (int ch = 0; ch < 8; ch++) {
        const int colb = ch * 32;
        uint32_t r[32];
        TCGEN05_LD_32X32B_X32(r, tacc + colb);
        TCGEN05_WAIT_LD();
        const size_t base = (size_t)row * N + n0 + colb;
        const float4* bv = (const float4*)(bias + n0 + colb);
        if (MODE == 0) {
            uint4* dh = (uint4*)(Chi + base);
#pragma unroll
            for (int i = 0; i < 4; i++) {
                uint32_t hp[4];
#pragma unroll
                for (int p = 0; p < 4; p++) {
                    float4 b4 = bv[i * 2 + (p >> 1)];
                    float b0 = (p & 1) ? b4.z : b4.x;
                    float b1 = (p & 1) ? b4.w : b4.y;
                    float v0 = __uint_as_float(r[i*8+p*2+0]) + b0;
                    float v1 = __uint_as_float(r[i*8+p*2+1]) + b1;
                    float g0 = 0.5f * v0 * (1.f + erff(v0 * 0.70710678118654752f));
                    float g1 = 0.5f * v1 * (1.f + erff(v1 * 0.70710678118654752f));
                    hp[p] = (uint32_t)__bfloat16_as_ushort(__float2bfloat16(g0)) |
                            ((uint32_t)__bfloat16_as_ushort(__float2bfloat16(g1)) << 16);
                }
                dh[i] = make_uint4(hp[0], hp[1], hp[2], hp[3]);
            }
        } else {
            float4* dst = (float4*)(Cf + base);
#pragma unroll
            for (int i = 0; i < 8; i++) {
                float4 b4 = bv[i];
                float4 o;
                o.x = __uint_as_float(r[i*4+0]) + b4.x;
                o.y = __uint_as_float(r[i*4+1]) + b4.y;
                o.z = __uint_as_float(r[i*4+2]) + b4.z;
                o.w = __uint_as_float(r[i*4+3]) + b4.w;
                dst[i] = o;
            }
        }
    }
    TCGEN05_FENCE_BEFORE();
    __syncthreads();
    if (tid == 0) {
#pragma unroll
        for (int i = 0; i < 6; i++) { MBARRIER_INVAL(sb + 8 + i * 8); MBARRIER_INVAL(sb + 56 + i * 8); }
        MBARRIER_INVAL(sb + 104);
    }
    __syncthreads();
    if (wid == 0) TCGEN05_DEALLOC(tmem, 512);
#else
    const __nv_bfloat16* Ap = A + (size_t)((MODE == 0) ? 0 : z) * sA;
    const __nv_bfloat16* Bp = B + (size_t)z * sB;
    if (MODE == 0) Chi += z * sC;
    else           Cf  += z * sC;
    float* As = (float*)smx;
    float* Bs = As + 16 * 128;
    const int tid = threadIdx.x;
    const int tx = tid & 15, ty = tid >> 4;
    const int mr = ty * 8, nr = tx * 8;
    for (int mh = 0; mh < 2; mh++)
    for (int nh = 0; nh < 2; nh++) {
        const int m0 = blockIdx.y * 256 + mh * 128;
        const int n0 = blockIdx.x * 256 + nh * 128;
        float acc[8][8];
#pragma unroll
        for (int i = 0; i < 8; i++)
#pragma unroll
            for (int j = 0; j < 8; j++) acc[i][j] = 0.f;
        for (int k0 = 0; k0 < K; k0 += 16) {
            __syncthreads();
#pragma unroll
            for (int i = 0; i < 8; i++) {
                int idx = i * 256 + tid;
                int kk = idx >> 7, mm = idx & 127;
                size_t ga = (size_t)(m0 + mm) * K + k0 + kk;
                size_t gb = (size_t)(n0 + mm) * K + k0 + kk;
                As[kk*128+mm] = __bfloat162float(Ap[ga]);
                Bs[kk*128+mm] = __bfloat162float(Bp[gb]);
            }
            __syncthreads();
#pragma unroll
            for (int kk = 0; kk < 16; kk++) {
                float a0[8], b0[8];
#pragma unroll
                for (int i = 0; i < 8; i++) a0[i] = As[kk*128+mr+i];
#pragma unroll
                for (int j = 0; j < 8; j++) b0[j] = Bs[kk*128+nr+j];
#pragma unroll
                for (int i = 0; i < 8; i++)
#pragma unroll
                    for (int j = 0; j < 8; j++)
                        acc[i][j] = fmaf(a0[i], b0[j], acc[i][j]);
            }
        }
#pragma unroll
        for (int i = 0; i < 8; i++) {
            const int row = m0 + mr + i;
#pragma unroll
            for (int j = 0; j < 8; j++) {
                const int col = n0 + nr + j;
                const size_t idx = (size_t)row * N + col;
                float v = acc[i][j] + bias[col];
                if (MODE == 0) {
                    float g = 0.5f * v * (1.f + erff(v * 0.70710678118654752f));
                    Chi[idx] = __float2bfloat16(g);
                } else Cf[idx] = v;
            }
        }
    }
#endif
}

// ---------------- transpose v2 -------------------------------------------------------
__global__ void __launch_bounds__(256)
transpose_split(const float* __restrict__ W, __nv_bfloat16* __restrict__ Thi,
                __nv_bfloat16* __restrict__ Tlo, int K, int N)
{
    __shared__ float t[64][33];
    const int e = blockIdx.z;
    const float* Wp = W + (size_t)e * K * N;
    __nv_bfloat16* th = Thi + (size_t)e * K * N;
    __nv_bfloat16* tl = Tlo ? Tlo + (size_t)e * K * N : nullptr;
    const int k0 = blockIdx.x * 64, n0 = blockIdx.y * 32;
    const int tid = threadIdx.x;
#pragma unroll
    for (int i = 0; i < 8; i++) {
        int idx = i * 256 + tid;
        int r = idx >> 5, c = idx & 31;
        t[r][c] = Wp[(size_t)(k0 + r) * N + n0 + c];
    }
    __syncthreads();
#pragma unroll
    for (int i = 0; i < 4; i++) {
        int idx = i * 256 + tid;
        int c = idx >> 5, j = idx & 31;
        float v0 = t[2 * j][c], v1 = t[2 * j + 1][c];
        __nv_bfloat16 h0 = __float2bfloat16(v0);
        __nv_bfloat16 h1 = __float2bfloat16(v1);
        const size_t base = (size_t)(n0 + c) * K + k0 + 2 * j;
        *(uint32_t*)(th + base) =
            (uint32_t)__bfloat16_as_ushort(h0) | ((uint32_t)__bfloat16_as_ushort(h1) << 16);
        if (tl) {
            __nv_bfloat16 l0 = __float2bfloat16(v0 - __bfloat162float(h0));
            __nv_bfloat16 l1 = __float2bfloat16(v1 - __bfloat162float(h1));
            *(uint32_t*)(tl + base) =
                (uint32_t)__bfloat16_as_ushort(l0) | ((uint32_t)__bfloat16_as_ushort(l1) << 16);
        }
    }
}

// ---------------- batched q/k/v split ------------------------------------------------
__global__ void __launch_bounds__(256)
split3_bf16(const float* __restrict__ q, const float* __restrict__ k,
            const float* __restrict__ v, __nv_bfloat16* __restrict__ hi,
            __nv_bfloat16* __restrict__ lo, int n4)
{
    const int seg = blockIdx.y;
    const float* x = (seg == 0) ? q : (seg == 1) ? k : v;
    int i = blockIdx.x * 256 + threadIdx.x;
    if (i >= n4) return;
    float4 val = ((const float4*)x)[i];
    __nv_bfloat16 h0 = __float2bfloat16(val.x), h1 = __float2bfloat16(val.y);
    __nv_bfloat16 h2 = __float2bfloat16(val.z), h3 = __float2bfloat16(val.w);
    uint2 hp, lp;
    hp.x = (uint32_t)__bfloat16_as_ushort(h0) | ((uint32_t)__bfloat16_as_ushort(h1) << 16);
    hp.y = (uint32_t)__bfloat16_as_ushort(h2) | ((uint32_t)__bfloat16_as_ushort(h3) << 16);
    __nv_bfloat16 l0 = __float2bfloat16(val.x - __bfloat162float(h0));
    __nv_bfloat16 l1 = __float2bfloat16(val.y - __bfloat162float(h1));
    __nv_bfloat16 l2 = __float2bfloat16(val.z - __bfloat162float(h2));
    __nv_bfloat16 l3 = __float2bfloat16(val.w - __bfloat162float(h3));
    lp.x = (uint32_t)__bfloat16_as_ushort(l0) | ((uint32_t)__bfloat16_as_ushort(l1) << 16);
    lp.y = (uint32_t)__bfloat16_as_ushort(l2) | ((uint32_t)__bfloat16_as_ushort(l3) << 16);
    const size_t off = (size_t)seg * n4 + i;
    ((uint2*)hi)[off] = hp;
    ((uint2*)lo)[off] = lp;
}

// ---------------- attention v3: emits split-bf16 ctx directly -------------------------
#define ATT_V 28224
#define ATT_Q 78400
#define ATT_P 86592
#define ATT_SMEM 112192

__global__ void __launch_bounds__(256, 2)
attn_kernel(const float* __restrict__ qh, const float* __restrict__ kh,
            const float* __restrict__ vh,
            __nv_bfloat16* __restrict__ chi, __nv_bfloat16* __restrict__ clo)
{
    const int b = blockIdx.x / Hq;
    const int h = blockIdx.x % Hq;
    const int qbase = blockIdx.y * 49;
    const int qend  = min(196, qbase + 49);
    extern __shared__ __align__(16) char sm[];
    uint32_t* Ksp = (uint32_t*)sm;
    float* Vs = (float*)(sm + ATT_V);
    float* Qs = (float*)(sm + ATT_Q);
    float* Ps = (float*)(sm + ATT_P);
    const int tid = threadIdx.x;

    for (int i = tid; i < Sq * 32; i += 256) {
        int s = i >> 5, dp = i & 31;
        size_t g = (size_t)(b * Sq + s) * Dq + h * DHq + 2 * dp;
        float2 kv = *(const float2*)(kh + g);
        __nv_bfloat16 k0 = __float2bfloat16(kv.x), k1 = __float2bfloat16(kv.y);
        Ksp[s * 36 + dp] = (uint32_t)__bfloat16_as_ushort(k0) |
                           ((uint32_t)__bfloat16_as_ushort(k1) << 16);
        *(float2*)(Vs + s * 64 + 2 * dp) = *(const float2*)(vh + g);
    }
    __syncthreads();

    const int warp = tid >> 5, lane = tid & 31;
    float* Qw = Qs + warp * 256;
    float* Pw = Ps + warp * 800;

    for (int q0 = qbase + warp * 4; q0 < qend; q0 += 32) {
        const int nq = min(4, qend - q0);
#pragma unroll
        for (int qq = 0; qq < 4; qq++) {
            int qi = q0 + qq;
#pragma unroll
            for (int r = 0; r < 2; r++) {
                int d = lane + r * 32;
                Qw[qq * 64 + d] = (qi < qend) ?
                    qh[(size_t)(b * Sq + qi) * Dq + h * DHq + d] : 0.f;
            }
        }
        __syncwarp();

        float s4[4][7];
#pragma unroll
        for (int qq = 0; qq < 4; qq++)
#pragma unroll
            for (int c = 0; c < 7; c++) s4[qq][c] = 0.f;
#pragma unroll
        for (int d8 = 0; d8 < 8; d8++) {
            float qv[4][8];
#pragma unroll
            for (int qq = 0; qq < 4; qq++) {
                float4 a = *(float4*)(Qw + qq * 64 + d8 * 8);
                float4 bb = *(float4*)(Qw + qq * 64 + d8 * 8 + 4);
                qv[qq][0] = a.x;  qv[qq][1] = a.y;  qv[qq][2] = a.z;  qv[qq][3] = a.w;
                qv[qq][4] = bb.x; qv[qq][5] = bb.y; qv[qq][6] = bb.z; qv[qq][7] = bb.w;
            }
#pragma unroll
            for (int c = 0; c < 7; c++) {
                int col = lane + 32 * c;
                if (col < Sq) {
                    uint4 kp = *(uint4*)(Ksp + col * 36 + d8 * 4);
                    float kf[8];
                    kf[0] = __uint_as_float(kp.x << 16);
                    kf[1] = __uint_as_float(kp.x & 0xFFFF0000u);
                    kf[2] = __uint_as_float(kp.y << 16);
                    kf[3] = __uint_as_float(kp.y & 0xFFFF0000u);
                    kf[4] = __uint_as_float(kp.z << 16);
                    kf[5] = __uint_as_float(kp.z & 0xFFFF0000u);
                    kf[6] = __uint_as_float(kp.w << 16);
                    kf[7] = __uint_as_float(kp.w & 0xFFFF0000u);
#pragma unroll
                    for (int qq = 0; qq < 4; qq++) {
                        float s = s4[qq][c];
#pragma unroll
                        for (int e = 0; e < 8; e++) s = fmaf(kf[e], qv[qq][e], s);
                        s4[qq][c] = s;
                    }
                }
            }
        }

        float inv[4];
#pragma unroll
        for (int qq = 0; qq < 4; qq++) {
            float m = -1e30f;
#pragma unroll
            for (int c = 0; c < 7; c++) {
                int col = lane + 32 * c;
                if (col < Sq) m = fmaxf(m, s4[qq][c] * 0.125f);
            }
#pragma unroll
            for (int o = 16; o; o >>= 1) m = fmaxf(m, __shfl_xor_sync(0xffffffffu, m, o));
            float sum = 0.f;
#pragma unroll
            for (int c = 0; c < 7; c++) {
                int col = lane + 32 * c;
                if (col < Sq) {
                    float e = __expf(s4[qq][c] * 0.125f - m);
                    Pw[qq * 200 + col] = e;
                    sum += e;
                }
            }
#pragma unroll
            for (int o = 16; o; o >>= 1) sum += __shfl_xor_sync(0xffffffffu, sum, o);
            inv[qq] = 1.f / sum;
        }
        __syncwarp();

        float acc[4][2];
#pragma unroll
        for (int qq = 0; qq < 4; qq++) { acc[qq][0] = 0.f; acc[qq][1] = 0.f; }
        for (int k4 = 0; k4 < Sq; k4 += 4) {
            float pa[4][4];
#pragma unroll
            for (int qq = 0; qq < 4; qq++) {
                float4 p = *(float4*)(Pw + qq * 200 + k4);
                pa[qq][0] = p.x; pa[qq][1] = p.y; pa[qq][2] = p.z; pa[qq][3] = p.w;
            }
#pragma unroll
            for (int j = 0; j < 4; j++) {
                float2 vv = *(float2*)(Vs + (k4 + j) * 64 + 2 * lane);
#pragma unroll
                for (int qq = 0; qq < 4; qq++) {
                    acc[qq][0] = fmaf(pa[qq][j], vv.x, acc[qq][0]);
                    acc[qq][1] = fmaf(pa[qq][j], vv.y, acc[qq][1]);
                }
            }
        }
#pragma unroll
        for (int qq = 0; qq < 4; qq++) {
            if (qq < nq) {
                float ox = acc[qq][0] * inv[qq];
                float oy = acc[qq][1] * inv[qq];
                __nv_bfloat16 h0 = __float2bfloat16(ox);
                __nv_bfloat16 h1 = __float2bfloat16(oy);
                __nv_bfloat16 l0 = __float2bfloat16(ox - __bfloat162float(h0));
                __nv_bfloat16 l1 = __float2bfloat16(oy - __bfloat162float(h1));
                const size_t idx = (size_t)(b * Sq + q0 + qq) * Dq + h * DHq + 2 * lane;
                *(uint32_t*)(chi + idx) =
                    (uint32_t)__bfloat16_as_ushort(h0) | ((uint32_t)__bfloat16_as_ushort(h1) << 16);
                *(uint32_t*)(clo + idx) =
                    (uint32_t)__bfloat16_as_ushort(l0) | ((uint32_t)__bfloat16_as_ushort(l1) << 16);
            }
        }
        __syncwarp();
    }
}

// ---------------- LN1 + gate fused (emits bf16 hi + gates) ----------------------------
__global__ void __launch_bounds__(256)
ln_gate_kernel(const float* __restrict__ a, const float* __restrict__ g,
               const float* __restrict__ be, const float* __restrict__ Wg,
               const float* __restrict__ bg, float* __restrict__ out,
               __nv_bfloat16* __restrict__ ohi, float* __restrict__ gates)
{
    const int row = blockIdx.x;
    const float* ar = a + (size_t)row * Dq;
    float v[3];
    float s = 0.f, s2 = 0.f;
#pragma unroll
    for (int i = 0; i < 3; i++) {
        int d = threadIdx.x + i * 256;
        float x = ar[d];
        v[i] = x;
        s += x; s2 = fmaf(x, x, s2);
    }
    __shared__ float rs[8], rs2[8];
#pragma unroll
    for (int o = 16; o; o >>= 1) { s += __shfl_xor_sync(0xffffffffu, s, o); s2 += __shfl_xor_sync(0xffffffffu, s2, o); }
    const int warp = threadIdx.x >> 5, lane = threadIdx.x & 31;
    if (lane == 0) { rs[warp] = s; rs2[warp] = s2; }
    __syncthreads();
    if (warp == 0) {
        float t  = (lane < 8) ? rs[lane]  : 0.f;
        float t2 = (lane < 8) ? rs2[lane] : 0.f;
#pragma unroll
        for (int o = 4; o; o >>= 1) { t += __shfl_xor_sync(0xffffffffu, t, o); t2 += __shfl_xor_sync(0xffffffffu, t2, o); }
        if (lane == 0) { rs[0] = t; rs2[0] = t2; }
    }
    __syncthreads();
    const float mu  = rs[0] * (1.f / Dq);
    const float var = rs2[0] * (1.f / Dq) - mu * mu;
    const float inv = rsqrtf(var + 1e-5f);

    float lg[Eq];
#pragma unroll
    for (int e = 0; e < Eq; e++) lg[e] = 0.f;
#pragma unroll
    for (int i = 0; i < 3; i++) {
        int d = threadIdx.x + i * 256;
        float y = (v[i] - mu) * inv * g[d] + be[d];
        const size_t idx = (size_t)row * Dq + d;
        out[idx] = y;
        ohi[idx] = __float2bfloat16(y);
        const float4* wg4 = (const float4*)(Wg + (size_t)d * Eq);
        float4 w0 = wg4[0], w1 = wg4[1];
        lg[0] = fmaf(y, w0.x, lg[0]); lg[1] = fmaf(y, w0.y, lg[1]);
        lg[2] = fmaf(y, w0.z, lg[2]); lg[3] = fmaf(y, w0.w, lg[3]);
        lg[4] = fmaf(y, w1.x, lg[4]); lg[5] = fmaf(y, w1.y, lg[5]);
        lg[6] = fmaf(y, w1.z, lg[6]); lg[7] = fmaf(y, w1.w, lg[7]);
    }
    // reduce 8 logits across warp, then across warps
#pragma unroll
    for (int e = 0; e < Eq; e++)
#pragma unroll
        for (int o = 16; o; o >>= 1) lg[e] += __shfl_xor_sync(0xffffffffu, lg[e], o);
    __shared__ float gsum[8][Eq];
    if (lane == 0)
#pragma unroll
        for (int e = 0; e < Eq; e++) gsum[warp][e] = lg[e];
    __syncthreads();
    if (threadIdx.x == 0) {
        float tot[Eq];
        float m = -1e30f;
#pragma unroll
        for (int e = 0; e < Eq; e++) {
            float t = bg[e];
#pragma unroll
            for (int w = 0; w < 8; w++) t += gsum[w][e];
            tot[e] = t;
            m = fmaxf(m, t);
        }
        float sum = 0.f;
#pragma unroll
        for (int e = 0; e < Eq; e++) { tot[e] = __expf(tot[e] - m); sum += tot[e]; }
        float is = 1.f / sum;
#pragma unroll
        for (int e = 0; e < Eq; e++) gates[(size_t)row * Eq + e] = tot[e] * is;
    }
}

// ---------------- LN2: fused gate-weighted expert reduction --------------------------
__global__ void __launch_bounds__(256)
ln2_kernel(const float* __restrict__ x, const float* __restrict__ y,
           const float* __restrict__ gates, const float* __restrict__ g,
           const float* __restrict__ be, float* __restrict__ out)
{
    const int row = blockIdx.x;
    __shared__ float sg[Eq];
    if (threadIdx.x < Eq) sg[threadIdx.x] = gates[(size_t)row * Eq + threadIdx.x];
    __syncthreads();
    float v[3];
    float s = 0.f, s2 = 0.f;
#pragma unroll
    for (int i = 0; i < 3; i++) {
        int d = threadIdx.x + i * 256;
        float val = x[(size_t)row * Dq + d];
#pragma unroll
        for (int e = 0; e < Eq; e++)
            val = fmaf(sg[e], y[(size_t)e * MPAD * Dq + (size_t)row * Dq + d], val);
        v[i] = val;
        s += val; s2 = fmaf(val, val, s2);
    }
    __shared__ float rs[8], rs2[8];
#pragma unroll
    for (int o = 16; o; o >>= 1) { s += __shfl_xor_sync(0xffffffffu, s, o); s2 += __shfl_xor_sync(0xffffffffu, s2, o); }
    const int warp = threadIdx.x >> 5, lane = threadIdx.x & 31;
    if (lane == 0) { rs[warp] = s; rs2[warp] = s2; }
    __syncthreads();
    if (warp == 0) {
        float t  = (lane < 8) ? rs[lane]  : 0.f;
        float t2 = (lane < 8) ? rs2[lane] : 0.f;
#pragma unroll
        for (int o = 4; o; o >>= 1) { t += __shfl_xor_sync(0xffffffffu, t, o); t2 += __shfl_xor_sync(0xffffffffu, t2, o); }
        if (lane == 0) { rs[0] = t; rs2[0] = t2; }
    }
    __syncthreads();
    const float mu  = rs[0] * (1.f / Dq);
    const float var = rs2[0] * (1.f / Dq) - mu * mu;
    const float inv = rsqrtf(var + 1e-5f);
#pragma unroll
    for (int i = 0; i < 3; i++) {
        int d = threadIdx.x + i * 256;
        out[(size_t)row * Dq + d] = (v[i] - mu) * inv * g[d] + be[d];
    }
}

// ====================================================================================
typedef CUresult (*EncFn)(CUtensorMap*, CUtensorMapDataType, cuuint32_t, void*,
                          const cuuint64_t*, const cuuint64_t*, const cuuint32_t*,
                          const cuuint32_t*, CUtensorMapInterleave, CUtensorMapSwizzle,
                          CUtensorMapL2promotion, CUtensorMapFloatOOBfill);

static void make_map(EncFn enc, CUtensorMap* m, void* ptr,
                     uint64_t d0, uint64_t d1, uint64_t d2)
{
    cuuint64_t dims[3] = {d0, d1, d2};
    cuuint64_t strides[2] = {d0 * 2, d0 * d1 * 2};
    cuuint32_t box[3] = {32, 256, 1};
    cuuint32_t es[3] = {1, 1, 1};
    enc(m, CU_TENSOR_MAP_DATA_TYPE_BFLOAT16, 3, ptr, dims, strides, box, es,
        CU_TENSOR_MAP_INTERLEAVE_NONE, CU_TENSOR_MAP_SWIZZLE_64B,
        CU_TENSOR_MAP_L2_PROMOTION_L2_128B, CU_TENSOR_MAP_FLOAT_OOB_FILL_NONE);
}

extern "C" void kernel_launch(void* const* d_in, const int* in_sizes, int n_in,
                              void* d_out, int out_size)
{
    const float* q   = (const float*)d_in[0];
    const float* k   = (const float*)d_in[1];
    const float* v   = (const float*)d_in[2];
    const float* Wq  = (const float*)d_in[3];
    const float* bq  = (const float*)d_in[4];
    const float* Wk  = (const float*)d_in[5];
    const float* bk  = (const float*)d_in[6];
    const float* Wv  = (const float*)d_in[7];
    const float* bv  = (const float*)d_in[8];
    const float* Wo  = (const float*)d_in[9];
    const float* bo  = (const float*)d_in[10];
    const float* ln1g= (const float*)d_in[11];
    const float* ln1b= (const float*)d_in[12];
    const float* ln2g= (const float*)d_in[13];
    const float* ln2b= (const float*)d_in[14];
    const float* Wg  = (const float*)d_in[15];
    const float* bg  = (const float*)d_in[16];
    const float* W1  = (const float*)d_in[17];
    const float* b1  = (const float*)d_in[18];
    const float* W2  = (const float*)d_in[19];
    const float* b2  = (const float*)d_in[20];
    float* out = (float*)d_out;

    float *p_qkvh, *p_tmp, *p_x, *p_y, *p_gates;
    __nv_bfloat16 *p_inhi, *p_inlo, *p_xhi, *p_hhi, *p_qlo;
    __nv_bfloat16 *p_w1h, *p_w2h, *p_wqkvh, *p_wqkvl, *p_woh, *p_wol;
    cudaGetSymbolAddress((void**)&p_qkvh, d_qkvh);
    cudaGetSymbolAddress((void**)&p_tmp,  d_tmp);
    cudaGetSymbolAddress((void**)&p_x,    d_x);
    cudaGetSymbolAddress((void**)&p_y,    d_y);
    cudaGetSymbolAddress((void**)&p_gates,d_gates);
    cudaGetSymbolAddress((void**)&p_inhi, d_inhi);
    cudaGetSymbolAddress((void**)&p_inlo, d_inlo);
    cudaGetSymbolAddress((void**)&p_xhi,  d_xhi);
    cudaGetSymbolAddress((void**)&p_hhi,  d_hhi);
    cudaGetSymbolAddress((void**)&p_qlo,  d_qlo);
    cudaGetSymbolAddress((void**)&p_w1h,  d_w1t_hi);
    cudaGetSymbolAddress((void**)&p_w2h,  d_w2t_hi);
    cudaGetSymbolAddress((void**)&p_wqkvh, d_wqkvt_hi);
    cudaGetSymbolAddress((void**)&p_wqkvl, d_wqkvt_lo);
    cudaGetSymbolAddress((void**)&p_woh,  d_wot_hi);
    cudaGetSymbolAddress((void**)&p_wol,  d_wot_lo);

    static EncFn enc = nullptr;
    static cudaStream_t s2 = nullptr;
    static cudaEvent_t evFork = nullptr, evJoin = nullptr;
    if (!enc) {
        void* fp = nullptr;
        cudaDriverEntryPointQueryResult st;
        cudaGetDriverEntryPointByVersion("cuTensorMapEncodeTiled", &fp, 12000,
                                         cudaEnableDefault, &st);
        enc = (EncFn)fp;
        cudaStreamCreateWithFlags(&s2, cudaStreamNonBlocking);
        cudaEventCreateWithFlags(&evFork, cudaEventDisableTiming);
        cudaEventCreateWithFlags(&evJoin, cudaEventDisableTiming);
    }
    CUtensorMap mXh, mHh, mW1h, mW2h;
    make_map(enc, &mXh, p_xhi, Dq, MPAD, 1);
    make_map(enc, &mHh, p_hhi, Fq, MPAD, Eq);
    make_map(enc, &mW1h, p_w1h, Dq, Fq, Eq);
    make_map(enc, &mW2h, p_w2h, Fq, Dq, Eq);

    const dim3 blk(256);
    const dim3 gridQKV(Dq / TN, NTOK / TM, 3);
    const dim3 gridO(Dq / TN, NTOK / TM, 1);
    const dim3 grid1(Fq / 256, MPAD / 256, Eq);
    const dim3 grid2(Dq / 256, MPAD / 256, Eq);
    const int n4 = NTOK * Dq / 4;
    const int sgrid = (n4 + 255) / 256;
    const size_t segQ = (size_t)NTOK * Dq;

    cudaFuncSetAttribute(tc_gemm<2>,  cudaFuncAttributeMaxDynamicSharedMemorySize, TC_SMEM);
    cudaFuncSetAttribute(tc_gemm<3>,  cudaFuncAttributeMaxDynamicSharedMemorySize, TC_SMEM);
    cudaFuncSetAttribute(tc_gemm2<0>, cudaFuncAttributeMaxDynamicSharedMemorySize, TC2_SMEM);
    cudaFuncSetAttribute(tc_gemm2<1>, cudaFuncAttributeMaxDynamicSharedMemorySize, TC2_SMEM);
    cudaFuncSetAttribute(attn_kernel, cudaFuncAttributeMaxDynamicSharedMemorySize, ATT_SMEM);

    __nv_bfloat16* p_qkvshi = p_hhi;   // qkv-hi staging in idle h region

    // --- fork: W1/W2 transposes on s2, joined before GEMM1 ---
    cudaEventRecord(evFork, 0);
    cudaStreamWaitEvent(s2, evFork, 0);
    transpose_split<<<dim3(Dq/64, Fq/32, Eq), blk, 0, s2>>>(W1, p_w1h, nullptr, Dq, Fq);
    transpose_split<<<dim3(Fq/64, Dq/32, Eq), blk, 0, s2>>>(W2, p_w2h, nullptr, Fq, Dq);
    cudaEventRecord(evJoin, s2);

    // --- main chain ---
    transpose_split<<<dim3(Dq/64, Dq/32, 1), blk>>>(Wq, p_wqkvh,           p_wqkvl,           Dq, Dq);
    transpose_split<<<dim3(Dq/64, Dq/32, 1), blk>>>(Wk, p_wqkvh + Dq*Dq,   p_wqkvl + Dq*Dq,   Dq, Dq);
    transpose_split<<<dim3(Dq/64, Dq/32, 1), blk>>>(Wv, p_wqkvh + 2*Dq*Dq, p_wqkvl + 2*Dq*Dq, Dq, Dq);
    split3_bf16<<<dim3(sgrid, 3), blk>>>(q, k, v, p_qkvshi, p_qlo, n4);
    tc_gemm<2><<<gridQKV, blk, TC_SMEM>>>(p_qkvshi, p_qlo, p_wqkvh, p_wqkvl,
                                          bq, bk, bv, nullptr, p_qkvh,
                                          NTOK, Dq, Dq, segQ, (size_t)Dq * Dq, segQ);
    attn_kernel<<<dim3(Bq * Hq, 4), blk, ATT_SMEM>>>(p_qkvh, p_qkvh + segQ, p_qkvh + 2 * segQ,
                                                     p_inhi, p_inlo);
    transpose_split<<<dim3(Dq/64, Dq/32, 1), blk>>>(Wo, p_woh, p_wol, Dq, Dq);
    tc_gemm<3><<<gridO, blk, TC_SMEM>>>(p_inhi, p_inlo, p_woh, p_wol,
                                        bo, bo, bo, q, p_tmp, NTOK, Dq, Dq, 0, 0, 0);
    ln_gate_kernel<<<NTOK, blk>>>(p_tmp, ln1g, ln1b, Wg, bg, p_x, p_xhi, p_gates);

    // --- join; MoE ---
    cudaStreamWaitEvent(0, evJoin, 0);
    tc_gemm2<0><<<grid1, blk, TC2_SMEM>>>(
        mXh, mW1h, b1, nullptr, p_hhi,
        Fq, Dq, (size_t)Fq, (size_t)MPAD * Fq,
        p_xhi, p_w1h, (size_t)0, (size_t)Fq * Dq);
    tc_gemm2<1><<<grid2, blk, TC2_SMEM>>>(
        mHh, mW2h, b2, p_y, nullptr,
        Dq, Fq, (size_t)Dq, (size_t)MPAD * Dq,
        p_hhi, p_w2h, (size_t)MPAD * Fq, (size_t)Dq * Fq);

    ln2_kernel<<<NTOK, blk>>>(p_x, p_y, p_gates, ln2g, ln2b, out);
}

// round 14
// speedup vs baseline: 11.9916x; 1.0286x over previous
#include <cuda_runtime.h>
#include <cuda.h>
#include <cuda_bf16.h>
#include <math.h>
#include <stdint.h>

#define Bq 32
#define Sq 196
#define Dq 768
#define Hq 12
#define Eq 8
#define Fq 3072
#define DHq 64
#define NTOK (Bq*Sq)
#define MPAD 6400

#define HAS_TCGEN05 (defined(__CUDA_ARCH_FEAT_SM103_ALL) || defined(__CUDA_ARCH_FEAT_SM100_ALL))

// ---------------- scratch ------------------------------------------------------
__device__ __align__(256) float d_qkvh[3*NTOK*Dq];
__device__ __align__(256) float d_tmp[NTOK*Dq];
__device__ __align__(256) float d_x  [NTOK*Dq];
__device__ __align__(256) float d_y  [Eq*MPAD*Dq];
__device__ __align__(256) float d_gates[MPAD*Eq];

__device__ __align__(256) __nv_bfloat16 d_inhi[NTOK*Dq];    // ctx bf16 (attention out)
__device__ __align__(256) __nv_bfloat16 d_xhi[MPAD*Dq];
__device__ __align__(256) __nv_bfloat16 d_hhi[Eq*MPAD*Fq];  // h; also qkv-hi staging early
__device__ __align__(256) __nv_bfloat16 d_w1t_hi[Eq*Fq*Dq];
__device__ __align__(256) __nv_bfloat16 d_w2t_hi[Eq*Dq*Fq];
__device__ __align__(256) __nv_bfloat16 d_wqkvt_hi[3*Dq*Dq];
__device__ __align__(256) __nv_bfloat16 d_wot_hi[Dq*Dq];

// ---------------- PTX helpers ---------------------------------------------------
__device__ __forceinline__ uint32_t smem_u32(const void* p) {
    uint32_t a;
    asm("{ .reg .u64 t; cvta.to.shared.u64 t, %1; cvt.u32.u64 %0, t; }" : "=r"(a) : "l"(p));
    return a;
}

#if HAS_TCGEN05
__device__ __forceinline__ bool elect_one() {
    uint32_t p;
    asm volatile("{\n .reg .pred p;\n elect.sync _|p, 0xFFFFFFFF;\n selp.b32 %0,1,0,p;\n}" : "=r"(p));
    return p != 0;
}
#define MBARRIER_INIT(addr, cnt) \
    asm volatile("mbarrier.init.shared.b64 [%0], %1;" :: "r"((uint32_t)(addr)), "r"((uint32_t)(cnt)) : "memory")
#define MBARRIER_INVAL(addr) \
    asm volatile("mbarrier.inval.shared.b64 [%0];" :: "r"((uint32_t)(addr)) : "memory")
#define MBARRIER_EXPECT_TX(addr, tx) \
    asm volatile("mbarrier.arrive.expect_tx.shared.b64 _, [%0], %1;" \
        :: "r"((uint32_t)(addr)), "r"((uint32_t)(tx)) : "memory")
#define MBARRIER_WAIT_PARITY(mbar, par) do { \
    uint32_t _m = (uint32_t)(mbar), _p = (uint32_t)(par), _d; \
    asm volatile("{\n\t.reg .pred p;\n\t" \
        "mbarrier.try_wait.parity.acquire.cta.shared::cta.b64 p, [%1], %2;\n\t" \
        "selp.b32 %0, 1, 0, p;\n\t}" : "=r"(_d) : "r"(_m), "r"(_p) : "memory"); \
    if (!_d) { \
        asm volatile("{\n\t.reg .pred P1;\n\t" \
            "WL_%=:\n\t" \
            "mbarrier.try_wait.parity.acquire.cta.shared::cta.b64 P1, [%0], %1, 0x989680;\n\t" \
            "@P1 bra.uni WD_%=;\n\tbra.uni WL_%=;\n\tWD_%=:\n\t}" \
            :: "r"(_m), "r"(_p) : "memory"); \
    } \
} while(0)
#define TCGEN05_ALLOC(a, n) \
    asm volatile("tcgen05.alloc.cta_group::1.sync.aligned.shared::cta.b32 [%0], %1;" \
        :: "r"((uint32_t)(a)), "r"((uint32_t)(n)) : "memory")
#define TCGEN05_DEALLOC(t, n) \
    asm volatile("tcgen05.dealloc.cta_group::1.sync.aligned.b32 %0, %1;" :: "r"(t), "r"(n))
#define TCGEN05_RELINQ() \
    asm volatile("tcgen05.relinquish_alloc_permit.cta_group::1.sync.aligned;")
#define TCGEN05_COMMIT(m) \
    asm volatile("tcgen05.commit.cta_group::1.mbarrier::arrive::one.shared::cluster.b64 [%0];" \
        :: "r"((uint32_t)(m)) : "memory")
#define TCGEN05_FENCE_AFTER()  asm volatile("tcgen05.fence::after_thread_sync;" ::: "memory")
#define TCGEN05_FENCE_BEFORE() asm volatile("tcgen05.fence::before_thread_sync;" ::: "memory")
#define TCGEN05_WAIT_LD() asm volatile("tcgen05.wait::ld.sync.aligned;" ::: "memory")
#define FENCE_ASYNC_SHARED() asm volatile("fence.proxy.async.shared::cta;" ::: "memory")
#define CP_ASYNC16(dst, src) \
    asm volatile("cp.async.cg.shared.global [%0], [%1], 16;" :: "r"((uint32_t)(dst)), "l"(src))
#define CP_COMMIT() asm volatile("cp.async.commit_group;" ::: "memory")
#define CP_WAIT(n)  asm volatile("cp.async.wait_group %0;" :: "n"(n) : "memory")
#define TMA_LOAD_3D(sm, map, cx, cy, cz, mb) \
    asm volatile("cp.async.bulk.tensor.3d.shared::cta.global.tile.mbarrier::complete_tx::bytes " \
        "[%0], [%1, {%2, %3, %4}], [%5];" \
        :: "r"((uint32_t)(sm)), "l"(map), "r"((int32_t)(cx)), "r"((int32_t)(cy)), \
           "r"((int32_t)(cz)), "r"((uint32_t)(mb)) : "memory")
#define TCGEN05_LD_32X32B_X32(r, ta) \
    asm volatile("tcgen05.ld.sync.aligned.32x32b.x32.b32 " \
        "{%0, %1, %2, %3, %4, %5, %6, %7, %8, %9, %10, %11, %12, %13, %14, %15, " \
        " %16, %17, %18, %19, %20, %21, %22, %23, %24, %25, %26, %27, %28, %29, %30, %31}, [%32];" \
        : "=r"((r)[0]), "=r"((r)[1]), "=r"((r)[2]), "=r"((r)[3]), "=r"((r)[4]), "=r"((r)[5]), \
          "=r"((r)[6]), "=r"((r)[7]), "=r"((r)[8]), "=r"((r)[9]), "=r"((r)[10]), "=r"((r)[11]), \
          "=r"((r)[12]), "=r"((r)[13]), "=r"((r)[14]), "=r"((r)[15]), "=r"((r)[16]), "=r"((r)[17]), \
          "=r"((r)[18]), "=r"((r)[19]), "=r"((r)[20]), "=r"((r)[21]), "=r"((r)[22]), "=r"((r)[23]), \
          "=r"((r)[24]), "=r"((r)[25]), "=r"((r)[26]), "=r"((r)[27]), "=r"((r)[28]), "=r"((r)[29]), \
          "=r"((r)[30]), "=r"((r)[31]) : "r"(ta))

static constexpr uint64_t DESC_SW128 =
    (uint64_t(2) << 61) | (uint64_t(1) << 46) | (uint64_t(64) << 32) | (uint64_t(1) << 16);
static constexpr uint64_t DESC_SW64 =
    (uint64_t(4) << 61) | (uint64_t(1) << 46) | (uint64_t(32) << 32) | (uint64_t(1) << 16);
#define MKD128(a) (DESC_SW128 | ((uint64_t)((a) >> 4) & 0x3FFF))
#define MKD64(a)  (DESC_SW64  | ((uint64_t)((a) >> 4) & 0x3FFF))

__device__ __forceinline__ void mma_bf16_ss(uint32_t d, uint64_t ad, uint64_t bd,
                                            uint32_t idesc, uint32_t en) {
    asm volatile(
        "{\n\t.reg .pred p;\n\tsetp.ne.u32 p, %5, 0;\n\t"
        "tcgen05.mma.cta_group::1.kind::f16 [%0], %1, %2, %3, {%4,%4,%4,%4}, p;\n\t}"
        :: "r"(d), "l"(ad), "l"(bd), "r"(idesc), "r"(0u), "r"(en) : "memory");
}
static constexpr uint32_t IDESC_BF16 =
    (1u << 4) | (1u << 7) | (1u << 10) | ((256 / 8) << 17) | ((128 / 16) << 24);
#endif

// ======================= TM128 tc GEMM (QKV batched / O-proj, pure bf16) ========
#define TM 128
#define TN 256
#define TK 64
#define STG128 49152
#define SM_DATA 1024
#define TC_SMEM (SM_DATA + 2*STG128)   // 99328

#if HAS_TCGEN05
__device__ __forceinline__ void load_slab128(
    uint32_t sbase, int stage,
    const __nv_bfloat16* __restrict__ A, const __nv_bfloat16* __restrict__ B,
    int m0, int n0, int k0, int K)
{
    const int tid = threadIdx.x;
    const uint32_t base = sbase + SM_DATA + stage * STG128;
#pragma unroll
    for (int i = 0; i < 4; i++) {
        int idx = i * 256 + tid;           // 0..1023 : A 128 rows x 64 bf16
        int row = idx >> 3, c4 = idx & 7;
        int off = row * 128 + c4 * 16;
        int sw  = off ^ ((off >> 3) & 0x70);
        size_t g = (size_t)(m0 + row) * K + k0 + c4 * 8;
        CP_ASYNC16(base + sw, A + g);
    }
#pragma unroll
    for (int i = 0; i < 8; i++) {
        int idx = i * 256 + tid;           // 0..2047 : B 256 rows x 64 bf16
        int row = idx >> 3, c4 = idx & 7;
        int off = row * 128 + c4 * 16;
        int sw  = off ^ ((off >> 3) & 0x70);
        size_t g = (size_t)(n0 + row) * K + k0 + c4 * 8;
        CP_ASYNC16(base + 16384 + sw, B + g);
    }
    CP_COMMIT();
}
#endif

template<int MODE>   // 2: z-batched C=AW+b(z)   3: C=AW+b+res
__global__ void __launch_bounds__(256)
tc_gemm(const __nv_bfloat16* __restrict__ A, const __nv_bfloat16* __restrict__ B,
        const float* __restrict__ b0, const float* __restrict__ b1,
        const float* __restrict__ b2, const float* __restrict__ res,
        float* __restrict__ Cf, int M, int N, int K,
        size_t sA, size_t sB, size_t sC)
{
    extern __shared__ __align__(1024) char smx[];
    const int z = blockIdx.z;
    A += z * sA; B += z * sB;
    Cf += z * sC;
    const float* bias = (z == 0) ? b0 : (z == 1) ? b1 : b2;
#if HAS_TCGEN05
    const uint32_t sb = smem_u32(smx);
    const int tid = threadIdx.x;
    const int wid = tid >> 5, lane = tid & 31;
    const int m0 = blockIdx.y * TM, n0 = blockIdx.x * TN;

    if (wid == 0) { TCGEN05_ALLOC(sb, 256); TCGEN05_RELINQ(); }
    if (tid == 0) { MBARRIER_INIT(sb + 8, 1); MBARRIER_INIT(sb + 16, 1); }
    __syncthreads();
    uint32_t tmem;
    asm volatile("ld.shared.b32 %0, [%1];" : "=r"(tmem) : "r"(sb));

    const int NS = K / TK;
    load_slab128(sb, 0, A, B, m0, n0, 0, K);
    int ph0 = 0, ph1 = 0;
    for (int s = 0; s < NS; s++) {
        const int buf = s & 1;
        if (s + 1 < NS) {
            const int nb = 1 - buf;
            if (s >= 1) {
                if (nb == 0) { MBARRIER_WAIT_PARITY(sb + 8,  ph0); ph0 ^= 1; }
                else         { MBARRIER_WAIT_PARITY(sb + 16, ph1); ph1 ^= 1; }
            }
            load_slab128(sb, nb, A, B, m0, n0, (s + 1) * TK, K);
            CP_WAIT(1);
        } else {
            CP_WAIT(0);
        }
        FENCE_ASYNC_SHARED();
        __syncthreads();
        if (wid == 0) {
            TCGEN05_FENCE_AFTER();
            if (elect_one()) {
                const uint32_t tb = sb + SM_DATA + buf * STG128;
                const uint64_t ah = MKD128(tb);
                const uint64_t bh = MKD128(tb + 16384);
#pragma unroll
                for (int ks = 0; ks < 4; ks++) {
                    const uint32_t en0 = (s == 0 && ks == 0) ? 0u : 1u;
                    mma_bf16_ss(tmem, ah + ks * 2, bh + ks * 2, IDESC_BF16, en0);
                }
                TCGEN05_COMMIT(sb + 8 + buf * 8);
            }
        }
    }
    if (((NS - 1) & 1) == 0) { MBARRIER_WAIT_PARITY(sb + 8,  ph0); }
    else                     { MBARRIER_WAIT_PARITY(sb + 16, ph1); }
    TCGEN05_FENCE_AFTER();

    const int sub = wid & 3, cg = wid >> 2;
    const int row = m0 + sub * 32 + lane;
#pragma unroll
    for (int ch = 0; ch < 4; ch++) {
        const int colb = cg * 128 + ch * 32;
        uint32_t r[32];
        TCGEN05_LD_32X32B_X32(r, tmem + colb);
        TCGEN05_WAIT_LD();
        const size_t base = (size_t)row * N + n0 + colb;
        const float4* bv = (const float4*)(bias + n0 + colb);
        float4* dst = (float4*)(Cf + base);
        const float4* rv = (MODE == 3) ? (const float4*)(res + base) : nullptr;
#pragma unroll
        for (int i = 0; i < 8; i++) {
            float4 b4 = bv[i];
            float4 o;
            o.x = __uint_as_float(r[i*4+0]) + b4.x;
            o.y = __uint_as_float(r[i*4+1]) + b4.y;
            o.z = __uint_as_float(r[i*4+2]) + b4.z;
            o.w = __uint_as_float(r[i*4+3]) + b4.w;
            if (MODE == 3) { float4 t = rv[i]; o.x += t.x; o.y += t.y; o.z += t.z; o.w += t.w; }
            dst[i] = o;
        }
    }
    TCGEN05_FENCE_BEFORE();
    __syncthreads();
    if (tid == 0) { MBARRIER_INVAL(sb + 8); MBARRIER_INVAL(sb + 16); }
    __syncthreads();
    if (wid == 0) TCGEN05_DEALLOC(tmem, 256);
#else
    float* As = (float*)smx;
    float* Bs = As + 16 * 128;
    const int tid = threadIdx.x;
    const int m0 = blockIdx.y * TM, n0x = blockIdx.x * TN;
    const int tx = tid & 15, ty = tid >> 4;
    const int mr = ty * 8, nr = tx * 8;
    for (int half = 0; half < 2; half++) {
        const int n0 = n0x + half * 128;
        float acc[8][8];
#pragma unroll
        for (int i = 0; i < 8; i++)
#pragma unroll
            for (int j = 0; j < 8; j++) acc[i][j] = 0.f;
        for (int k0 = 0; k0 < K; k0 += 16) {
            __syncthreads();
#pragma unroll
            for (int i = 0; i < 8; i++) {
                int idx = i * 256 + tid;
                int kk = idx >> 7, mm = idx & 127;
                size_t ga = (size_t)(m0 + mm) * K + k0 + kk;
                size_t gb = (size_t)(n0 + mm) * K + k0 + kk;
                As[kk*128+mm] = __bfloat162float(A[ga]);
                Bs[kk*128+mm] = __bfloat162float(B[gb]);
            }
            __syncthreads();
#pragma unroll
            for (int kk = 0; kk < 16; kk++) {
                float a0[8], b0r[8];
#pragma unroll
                for (int i = 0; i < 8; i++) a0[i] = As[kk*128+mr+i];
#pragma unroll
                for (int j = 0; j < 8; j++) b0r[j] = Bs[kk*128+nr+j];
#pragma unroll
                for (int i = 0; i < 8; i++)
#pragma unroll
                    for (int j = 0; j < 8; j++)
                        acc[i][j] = fmaf(a0[i], b0r[j], acc[i][j]);
            }
        }
#pragma unroll
        for (int i = 0; i < 8; i++) {
            const int row = m0 + mr + i;
#pragma unroll
            for (int j = 0; j < 8; j++) {
                const int col = n0 + nr + j;
                const size_t idx = (size_t)row * N + col;
                float v = acc[i][j] + bias[col];
                if (MODE == 2) Cf[idx] = v; else Cf[idx] = v + res[idx];
            }
        }
    }
#endif
}

// ======================= MoE GEMM: pure bf16, TMA producer/consumer =============
#define T2K 32
#define SLAB2 32768
#define TC2_SMEM (1024 + 6*SLAB2)   // 197632

template<int MODE>   // 0: gelu(acc+bias)->bf16   1: Cf = acc + bias
__global__ void __launch_bounds__(256)
tc_gemm2(const __grid_constant__ CUtensorMap mA, const __grid_constant__ CUtensorMap mB,
         const float* __restrict__ bias, float* __restrict__ Cf,
         __nv_bfloat16* __restrict__ Chi,
         int N, int K, size_t sBias, size_t sC,
         const __nv_bfloat16* __restrict__ A, const __nv_bfloat16* __restrict__ B,
         size_t sA, size_t sB)
{
    extern __shared__ __align__(1024) char smx[];
    const int z = blockIdx.z;
    bias += z * sBias;
#if HAS_TCGEN05
    const uint32_t sb = smem_u32(smx);
    const int tid = threadIdx.x;
    const int wid = tid >> 5, lane = tid & 31;
    const int m0 = blockIdx.y * 256, n0 = blockIdx.x * 256;
    const int za = (MODE == 0) ? 0 : z;

    if (wid == 0) { TCGEN05_ALLOC(sb, 512); TCGEN05_RELINQ(); }
    if (tid == 0) {
#pragma unroll
        for (int i = 0; i < 6; i++) { MBARRIER_INIT(sb + 8 + i * 8, 1); MBARRIER_INIT(sb + 56 + i * 8, 1); }
        MBARRIER_INIT(sb + 104, 1);
        FENCE_ASYNC_SHARED();
    }
    __syncthreads();
    uint32_t tmem;
    asm volatile("ld.shared.b32 %0, [%1];" : "=r"(tmem) : "r"(sb));

    const int NS = K / T2K;
    if (wid == 1) {
        if (elect_one()) {
            for (int s = 0; s < NS; s++) {
                const int st = s % 6;
                if (s >= 6) MBARRIER_WAIT_PARITY(sb + 56 + st * 8, ((s / 6) - 1) & 1);
                MBARRIER_EXPECT_TX(sb + 8 + st * 8, (uint32_t)SLAB2);
                const uint32_t stb = sb + 1024 + st * SLAB2;
                const int k0 = s * T2K;
                TMA_LOAD_3D(stb,         &mA, k0, m0, za, sb + 8 + st * 8);
                TMA_LOAD_3D(stb + 16384, &mB, k0, n0, z,  sb + 8 + st * 8);
            }
        }
    } else if (wid == 0) {
        TCGEN05_FENCE_AFTER();
        if (elect_one()) {
            for (int s = 0; s < NS; s++) {
                const int st = s % 6;
                MBARRIER_WAIT_PARITY(sb + 8 + st * 8, (s / 6) & 1);
                const uint32_t tb = sb + 1024 + st * SLAB2;
                const uint64_t a0 = MKD64(tb);
                const uint64_t a1 = a0 + 512;
                const uint64_t bh = MKD64(tb + 16384);
#pragma unroll
                for (int ks = 0; ks < 2; ks++) {
                    const uint32_t en0 = (s == 0 && ks == 0) ? 0u : 1u;
                    mma_bf16_ss(tmem,       a0 + ks * 2, bh + ks * 2, IDESC_BF16, en0);
                    mma_bf16_ss(tmem + 256, a1 + ks * 2, bh + ks * 2, IDESC_BF16, en0);
                }
                TCGEN05_COMMIT(sb + 56 + st * 8);
            }
            TCGEN05_COMMIT(sb + 104);
        }
    }

    MBARRIER_WAIT_PARITY(sb + 104, 0);
    TCGEN05_FENCE_AFTER();

    const int accSel = wid >> 2, sub = wid & 3;
    const int row = m0 + accSel * 128 + sub * 32 + lane;
    const uint32_t tacc = tmem + accSel * 256;
    if (MODE == 0) Chi += z * sC;
    else           Cf  += z * sC;
#pragma unroll
    for (int ch = 0; ch < 8; ch++) {
        const int colb = ch * 32;
        uint32_t r[32];
        TCGEN05_LD_32X32B_X32(r, tacc + colb);
        TCGEN05_WAIT_LD();
        const size_t base = (size_t)row * N + n0 + colb;
        const float4* bv = (const float4*)(bias + n0 + colb);
        if (MODE == 0) {
            uint4* dh = (uint4*)(Chi + base);
#pragma unroll
            for (int i = 0; i < 4; i++) {
                uint32_t hp[4];
#pragma unroll
                for (int p = 0; p < 4; p++) {
                    float4 b4 = bv[i * 2 + (p >> 1)];
                    float b0 = (p & 1) ? b4.z : b4.x;
                    float b1 = (p & 1) ? b4.w : b4.y;
                    float v0 = __uint_as_float(r[i*8+p*2+0]) + b0;
                    float v1 = __uint_as_float(r[i*8+p*2+1]) + b1;
                    float g0 = 0.5f * v0 * (1.f + erff(v0 * 0.70710678118654752f));
                    float g1 = 0.5f * v1 * (1.f + erff(v1 * 0.70710678118654752f));
                    hp[p] = (uint32_t)__bfloat16_as_ushort(__float2bfloat16(g0)) |
                            ((uint32_t)__bfloat16_as_ushort(__float2bfloat16(g1)) << 16);
                }
                dh[i] = make_uint4(hp[0], hp[1], hp[2], hp[3]);
            }
        } else {
            float4* dst = (float4*)(Cf + base);
#pragma unroll
            for (int i = 0; i < 8; i++) {
                float4 b4 = bv[i];
                float4 o;
                o.x = __uint_as_float(r[i*4+0]) + b4.x;
                o.y = __uint_as_float(r[i*4+1]) + b4.y;
                o.z = __uint_as_float(r[i*4+2]) + b4.z;
                o.w = __uint_as_float(r[i*4+3]) + b4.w;
                dst[i] = o;
            }
        }
    }
    TCGEN05_FENCE_BEFORE();
    __syncthreads();
    if (tid == 0) {
#pragma unroll
        for (int i = 0; i < 6; i++) { MBARRIER_INVAL(sb + 8 + i * 8); MBARRIER_INVAL(sb + 56 + i * 8); }
        MBARRIER_INVAL(sb + 104);
    }
    __syncthreads();
    if (wid == 0) TCGEN05_DEALLOC(tmem, 512);
#else
    const __nv_bfloat16* Ap = A + (size_t)((MODE == 0) ? 0 : z) * sA;
    const __nv_bfloat16* Bp = B + (size_t)z * sB;
    if (MODE == 0) Chi += z * sC;
    else           Cf  += z * sC;
    float* As = (float*)smx;
    float* Bs = As + 16 * 128;
    const int tid = threadIdx.x;
    const int tx = tid & 15, ty = tid >> 4;
    const int mr = ty * 8, nr = tx * 8;
    for (int mh = 0; mh < 2; mh++)
    for (int nh = 0; nh < 2; nh++) {
        const int m0 = blockIdx.y * 256 + mh * 128;
        const int n0 = blockIdx.x * 256 + nh * 128;
        float acc[8][8];
#pragma unroll
        for (int i = 0; i < 8; i++)
#pragma unroll
            for (int j = 0; j < 8; j++) acc[i][j] = 0.f;
        for (int k0 = 0; k0 < K; k0 += 16) {
            __syncthreads();
#pragma unroll
            for (int i = 0; i < 8; i++) {
                int idx = i * 256 + tid;
                int kk = idx >> 7, mm = idx & 127;
                size_t ga = (size_t)(m0 + mm) * K + k0 + kk;
                size_t gb = (size_t)(n0 + mm) * K + k0 + kk;
                As[kk*128+mm] = __bfloat162float(Ap[ga]);
                Bs[kk*128+mm] = __bfloat162float(Bp[gb]);
            }
            __syncthreads();
#pragma unroll
            for (int kk = 0; kk < 16; kk++) {
                float a0[8], b0[8];
#pragma unroll
                for (int i = 0; i < 8; i++) a0[i] = As[kk*128+mr+i];
#pragma unroll
                for (int j = 0; j < 8; j++) b0[j] = Bs[kk*128+nr+j];
#pragma unroll
                for (int i = 0; i < 8; i++)
#pragma unroll
                    for (int j = 0; j < 8; j++)
                        acc[i][j] = fmaf(a0[i], b0[j], acc[i][j]);
            }
        }
#pragma unroll
        for (int i = 0; i < 8; i++) {
            const int row = m0 + mr + i;
#pragma unroll
            for (int j = 0; j < 8; j++) {
                const int col = n0 + nr + j;
                const size_t idx = (size_t)row * N + col;
                float v = acc[i][j] + bias[col];
                if (MODE == 0) {
                    float g = 0.5f * v * (1.f + erff(v * 0.70710678118654752f));
                    Chi[idx] = __float2bfloat16(g);
                } else Cf[idx] = v;
            }
        }
    }
#endif
}

// ---------------- transpose v2 (hi only) ----------------------------------------------
__global__ void __launch_bounds__(256)
transpose_split(const float* __restrict__ W, __nv_bfloat16* __restrict__ Thi,
                int K, int N)
{
    __shared__ float t[64][33];
    const int e = blockIdx.z;
    const float* Wp = W + (size_t)e * K * N;
    __nv_bfloat16* th = Thi + (size_t)e * K * N;
    const int k0 = blockIdx.x * 64, n0 = blockIdx.y * 32;
    const int tid = threadIdx.x;
#pragma unroll
    for (int i = 0; i < 8; i++) {
        int idx = i * 256 + tid;
        int r = idx >> 5, c = idx & 31;
        t[r][c] = Wp[(size_t)(k0 + r) * N + n0 + c];
    }
    __syncthreads();
#pragma unroll
    for (int i = 0; i < 4; i++) {
        int idx = i * 256 + tid;
        int c = idx >> 5, j = idx & 31;
        float v0 = t[2 * j][c], v1 = t[2 * j + 1][c];
        __nv_bfloat16 h0 = __float2bfloat16(v0);
        __nv_bfloat16 h1 = __float2bfloat16(v1);
        const size_t base = (size_t)(n0 + c) * K + k0 + 2 * j;
        *(uint32_t*)(th + base) =
            (uint32_t)__bfloat16_as_ushort(h0) | ((uint32_t)__bfloat16_as_ushort(h1) << 16);
    }
}

// ---------------- batched q/k/v -> bf16 (hi only) --------------------------------------
__global__ void __launch_bounds__(256)
split3_bf16(const float* __restrict__ q, const float* __restrict__ k,
            const float* __restrict__ v, __nv_bfloat16* __restrict__ hi, int n4)
{
    const int seg = blockIdx.y;
    const float* x = (seg == 0) ? q : (seg == 1) ? k : v;
    int i = blockIdx.x * 256 + threadIdx.x;
    if (i >= n4) return;
    float4 val = ((const float4*)x)[i];
    __nv_bfloat16 h0 = __float2bfloat16(val.x), h1 = __float2bfloat16(val.y);
    __nv_bfloat16 h2 = __float2bfloat16(val.z), h3 = __float2bfloat16(val.w);
    uint2 hp;
    hp.x = (uint32_t)__bfloat16_as_ushort(h0) | ((uint32_t)__bfloat16_as_ushort(h1) << 16);
    hp.y = (uint32_t)__bfloat16_as_ushort(h2) | ((uint32_t)__bfloat16_as_ushort(h3) << 16);
    ((uint2*)hi)[(size_t)seg * n4 + i] = hp;
}

// ---------------- attention v4: emits bf16 ctx (hi only) ------------------------------
#define ATT_V 28224
#define ATT_Q 78400
#define ATT_P 86592
#define ATT_SMEM 112192

__global__ void __launch_bounds__(256, 2)
attn_kernel(const float* __restrict__ qh, const float* __restrict__ kh,
            const float* __restrict__ vh, __nv_bfloat16* __restrict__ chi)
{
    const int b = blockIdx.x / Hq;
    const int h = blockIdx.x % Hq;
    const int qbase = blockIdx.y * 49;
    const int qend  = min(196, qbase + 49);
    extern __shared__ __align__(16) char sm[];
    uint32_t* Ksp = (uint32_t*)sm;
    float* Vs = (float*)(sm + ATT_V);
    float* Qs = (float*)(sm + ATT_Q);
    float* Ps = (float*)(sm + ATT_P);
    const int tid = threadIdx.x;

    for (int i = tid; i < Sq * 32; i += 256) {
        int s = i >> 5, dp = i & 31;
        size_t g = (size_t)(b * Sq + s) * Dq + h * DHq + 2 * dp;
        float2 kv = *(const float2*)(kh + g);
        __nv_bfloat16 k0 = __float2bfloat16(kv.x), k1 = __float2bfloat16(kv.y);
        Ksp[s * 36 + dp] = (uint32_t)__bfloat16_as_ushort(k0) |
                           ((uint32_t)__bfloat16_as_ushort(k1) << 16);
        *(float2*)(Vs + s * 64 + 2 * dp) = *(const float2*)(vh + g);
    }
    __syncthreads();

    const int warp = tid >> 5, lane = tid & 31;
    float* Qw = Qs + warp * 256;
    float* Pw = Ps + warp * 800;

    for (int q0 = qbase + warp * 4; q0 < qend; q0 += 32) {
        const int nq = min(4, qend - q0);
#pragma unroll
        for (int qq = 0; qq < 4; qq++) {
            int qi = q0 + qq;
#pragma unroll
            for (int r = 0; r < 2; r++) {
                int d = lane + r * 32;
                Qw[qq * 64 + d] = (qi < qend) ?
                    qh[(size_t)(b * Sq + qi) * Dq + h * DHq + d] : 0.f;
            }
        }
        __syncwarp();

        float s4[4][7];
#pragma unroll
        for (int qq = 0; qq < 4; qq++)
#pragma unroll
            for (int c = 0; c < 7; c++) s4[qq][c] = 0.f;
#pragma unroll
        for (int d8 = 0; d8 < 8; d8++) {
            float qv[4][8];
#pragma unroll
            for (int qq = 0; qq < 4; qq++) {
                float4 a = *(float4*)(Qw + qq * 64 + d8 * 8);
                float4 bb = *(float4*)(Qw + qq * 64 + d8 * 8 + 4);
                qv[qq][0] = a.x;  qv[qq][1] = a.y;  qv[qq][2] = a.z;  qv[qq][3] = a.w;
                qv[qq][4] = bb.x; qv[qq][5] = bb.y; qv[qq][6] = bb.z; qv[qq][7] = bb.w;
            }
#pragma unroll
            for (int c = 0; c < 7; c++) {
                int col = lane + 32 * c;
                if (col < Sq) {
                    uint4 kp = *(uint4*)(Ksp + col * 36 + d8 * 4);
                    float kf[8];
                    kf[0] = __uint_as_float(kp.x << 16);
                    kf[1] = __uint_as_float(kp.x & 0xFFFF0000u);
                    kf[2] = __uint_as_float(kp.y << 16);
                    kf[3] = __uint_as_float(kp.y & 0xFFFF0000u);
                    kf[4] = __uint_as_float(kp.z << 16);
                    kf[5] = __uint_as_float(kp.z & 0xFFFF0000u);
                    kf[6] = __uint_as_float(kp.w << 16);
                    kf[7] = __uint_as_float(kp.w & 0xFFFF0000u);
#pragma unroll
                    for (int qq = 0; qq < 4; qq++) {
                        float s = s4[qq][c];
#pragma unroll
                        for (int e = 0; e < 8; e++) s = fmaf(kf[e], qv[qq][e], s);
                        s4[qq][c] = s;
                    }
                }
            }
        }

        float inv[4];
#pragma unroll
        for (int qq = 0; qq < 4; qq++) {
            float m = -1e30f;
#pragma unroll
            for (int c = 0; c < 7; c++) {
                int col = lane + 32 * c;
                if (col < Sq) m = fmaxf(m, s4[qq][c] * 0.125f);
            }
#pragma unroll
            for (int o = 16; o; o >>= 1) m = fmaxf(m, __shfl_xor_sync(0xffffffffu, m, o));
            float sum = 0.f;
#pragma unroll
            for (int c = 0; c < 7; c++) {
                int col = lane + 32 * c;
                if (col < Sq) {
                    float e = __expf(s4[qq][c] * 0.125f - m);
                    Pw[qq * 200 + col] = e;
                    sum += e;
                }
            }
#pragma unroll
            for (int o = 16; o; o >>= 1) sum += __shfl_xor_sync(0xffffffffu, sum, o);
            inv[qq] = 1.f / sum;
        }
        __syncwarp();

        float acc[4][2];
#pragma unroll
        for (int qq = 0; qq < 4; qq++) { acc[qq][0] = 0.f; acc[qq][1] = 0.f; }
        for (int k4 = 0; k4 < Sq; k4 += 4) {
            float pa[4][4];
#pragma unroll
            for (int qq = 0; qq < 4; qq++) {
                float4 p = *(float4*)(Pw + qq * 200 + k4);
                pa[qq][0] = p.x; pa[qq][1] = p.y; pa[qq][2] = p.z; pa[qq][3] = p.w;
            }
#pragma unroll
            for (int j = 0; j < 4; j++) {
                float2 vv = *(float2*)(Vs + (k4 + j) * 64 + 2 * lane);
#pragma unroll
                for (int qq = 0; qq < 4; qq++) {
                    acc[qq][0] = fmaf(pa[qq][j], vv.x, acc[qq][0]);
                    acc[qq][1] = fmaf(pa[qq][j], vv.y, acc[qq][1]);
                }
            }
        }
#pragma unroll
        for (int qq = 0; qq < 4; qq++) {
            if (qq < nq) {
                float ox = acc[qq][0] * inv[qq];
                float oy = acc[qq][1] * inv[qq];
                __nv_bfloat16 h0 = __float2bfloat16(ox);
                __nv_bfloat16 h1 = __float2bfloat16(oy);
                const size_t idx = (size_t)(b * Sq + q0 + qq) * Dq + h * DHq + 2 * lane;
                *(uint32_t*)(chi + idx) =
                    (uint32_t)__bfloat16_as_ushort(h0) | ((uint32_t)__bfloat16_as_ushort(h1) << 16);
            }
        }
        __syncwarp();
    }
}

// ---------------- LN1 + gate fused (emits bf16 hi + gates) ----------------------------
__global__ void __launch_bounds__(256)
ln_gate_kernel(const float* __restrict__ a, const float* __restrict__ g,
               const float* __restrict__ be, const float* __restrict__ Wg,
               const float* __restrict__ bg, float* __restrict__ out,
               __nv_bfloat16* __restrict__ ohi, float* __restrict__ gates)
{
    const int row = blockIdx.x;
    const float* ar = a + (size_t)row * Dq;
    float v[3];
    float s = 0.f, s2 = 0.f;
#pragma unroll
    for (int i = 0; i < 3; i++) {
        int d = threadIdx.x + i * 256;
        float x = ar[d];
        v[i] = x;
        s += x; s2 = fmaf(x, x, s2);
    }
    __shared__ float rs[8], rs2[8];
#pragma unroll
    for (int o = 16; o; o >>= 1) { s += __shfl_xor_sync(0xffffffffu, s, o); s2 += __shfl_xor_sync(0xffffffffu, s2, o); }
    const int warp = threadIdx.x >> 5, lane = threadIdx.x & 31;
    if (lane == 0) { rs[warp] = s; rs2[warp] = s2; }
    __syncthreads();
    if (warp == 0) {
        float t  = (lane < 8) ? rs[lane]  : 0.f;
        float t2 = (lane < 8) ? rs2[lane] : 0.f;
#pragma unroll
        for (int o = 4; o; o >>= 1) { t += __shfl_xor_sync(0xffffffffu, t, o); t2 += __shfl_xor_sync(0xffffffffu, t2, o); }
        if (lane == 0) { rs[0] = t; rs2[0] = t2; }
    }
    __syncthreads();
    const float mu  = rs[0] * (1.f / Dq);
    const float var = rs2[0] * (1.f / Dq) - mu * mu;
    const float inv = rsqrtf(var + 1e-5f);

    float lg[Eq];
#pragma unroll
    for (int e = 0; e < Eq; e++) lg[e] = 0.f;
#pragma unroll
    for (int i = 0; i < 3; i++) {
        int d = threadIdx.x + i * 256;
        float y = (v[i] - mu) * inv * g[d] + be[d];
        const size_t idx = (size_t)row * Dq + d;
        out[idx] = y;
        ohi[idx] = __float2bfloat16(y);
        const float4* wg4 = (const float4*)(Wg + (size_t)d * Eq);
        float4 w0 = wg4[0], w1 = wg4[1];
        lg[0] = fmaf(y, w0.x, lg[0]); lg[1] = fmaf(y, w0.y, lg[1]);
        lg[2] = fmaf(y, w0.z, lg[2]); lg[3] = fmaf(y, w0.w, lg[3]);
        lg[4] = fmaf(y, w1.x, lg[4]); lg[5] = fmaf(y, w1.y, lg[5]);
        lg[6] = fmaf(y, w1.z, lg[6]); lg[7] = fmaf(y, w1.w, lg[7]);
    }
#pragma unroll
    for (int e = 0; e < Eq; e++)
#pragma unroll
        for (int o = 16; o; o >>= 1) lg[e] += __shfl_xor_sync(0xffffffffu, lg[e], o);
    __shared__ float gsum[8][Eq];
    if (lane == 0)
#pragma unroll
        for (int e = 0; e < Eq; e++) gsum[warp][e] = lg[e];
    __syncthreads();
    if (threadIdx.x == 0) {
        float tot[Eq];
        float m = -1e30f;
#pragma unroll
        for (int e = 0; e < Eq; e++) {
            float t = bg[e];
#pragma unroll
            for (int w = 0; w < 8; w++) t += gsum[w][e];
            tot[e] = t;
            m = fmaxf(m, t);
        }
        float sum = 0.f;
#pragma unroll
        for (int e = 0; e < Eq; e++) { tot[e] = __expf(tot[e] - m); sum += tot[e]; }
        float is = 1.f / sum;
#pragma unroll
        for (int e = 0; e < Eq; e++) gates[(size_t)row * Eq + e] = tot[e] * is;
    }
}

// ---------------- LN2: fused gate-weighted expert reduction --------------------------
__global__ void __launch_bounds__(256)
ln2_kernel(const float* __restrict__ x, const float* __restrict__ y,
           const float* __restrict__ gates, const float* __restrict__ g,
           const float* __restrict__ be, float* __restrict__ out)
{
    const int row = blockIdx.x;
    __shared__ float sg[Eq];
    if (threadIdx.x < Eq) sg[threadIdx.x] = gates[(size_t)row * Eq + threadIdx.x];
    __syncthreads();
    float v[3];
    float s = 0.f, s2 = 0.f;
#pragma unroll
    for (int i = 0; i < 3; i++) {
        int d = threadIdx.x + i * 256;
        float val = x[(size_t)row * Dq + d];
#pragma unroll
        for (int e = 0; e < Eq; e++)
            val = fmaf(sg[e], y[(size_t)e * MPAD * Dq + (size_t)row * Dq + d], val);
        v[i] = val;
        s += val; s2 = fmaf(val, val, s2);
    }
    __shared__ float rs[8], rs2[8];
#pragma unroll
    for (int o = 16; o; o >>= 1) { s += __shfl_xor_sync(0xffffffffu, s, o); s2 += __shfl_xor_sync(0xffffffffu, s2, o); }
    const int warp = threadIdx.x >> 5, lane = threadIdx.x & 31;
    if (lane == 0) { rs[warp] = s; rs2[warp] = s2; }
    __syncthreads();
    if (warp == 0) {
        float t  = (lane < 8) ? rs[lane]  : 0.f;
        float t2 = (lane < 8) ? rs2[lane] : 0.f;
#pragma unroll
        for (int o = 4; o; o >>= 1) { t += __shfl_xor_sync(0xffffffffu, t, o); t2 += __shfl_xor_sync(0xffffffffu, t2, o); }
        if (lane == 0) { rs[0] = t; rs2[0] = t2; }
    }
    __syncthreads();
    const float mu  = rs[0] * (1.f / Dq);
    const float var = rs2[0] * (1.f / Dq) - mu * mu;
    const float inv = rsqrtf(var + 1e-5f);
#pragma unroll
    for (int i = 0; i < 3; i++) {
        int d = threadIdx.x + i * 256;
        out[(size_t)row * Dq + d] = (v[i] - mu) * inv * g[d] + be[d];
    }
}

// ====================================================================================
typedef CUresult (*EncFn)(CUtensorMap*, CUtensorMapDataType, cuuint32_t, void*,
                          const cuuint64_t*, const cuuint64_t*, const cuuint32_t*,
                          const cuuint32_t*, CUtensorMapInterleave, CUtensorMapSwizzle,
                          CUtensorMapL2promotion, CUtensorMapFloatOOBfill);

static void make_map(EncFn enc, CUtensorMap* m, void* ptr,
                     uint64_t d0, uint64_t d1, uint64_t d2)
{
    cuuint64_t dims[3] = {d0, d1, d2};
    cuuint64_t strides[2] = {d0 * 2, d0 * d1 * 2};
    cuuint32_t box[3] = {32, 256, 1};
    cuuint32_t es[3] = {1, 1, 1};
    enc(m, CU_TENSOR_MAP_DATA_TYPE_BFLOAT16, 3, ptr, dims, strides, box, es,
        CU_TENSOR_MAP_INTERLEAVE_NONE, CU_TENSOR_MAP_SWIZZLE_64B,
        CU_TENSOR_MAP_L2_PROMOTION_L2_128B, CU_TENSOR_MAP_FLOAT_OOB_FILL_NONE);
}

extern "C" void kernel_launch(void* const* d_in, const int* in_sizes, int n_in,
                              void* d_out, int out_size)
{
    const float* q   = (const float*)d_in[0];
    const float* k   = (const float*)d_in[1];
    const float* v   = (const float*)d_in[2];
    const float* Wq  = (const float*)d_in[3];
    const float* bq  = (const float*)d_in[4];
    const float* Wk  = (const float*)d_in[5];
    const float* bk  = (const float*)d_in[6];
    const float* Wv  = (const float*)d_in[7];
    const float* bv  = (const float*)d_in[8];
    const float* Wo  = (const float*)d_in[9];
    const float* bo  = (const float*)d_in[10];
    const float* ln1g= (const float*)d_in[11];
    const float* ln1b= (const float*)d_in[12];
    const float* ln2g= (const float*)d_in[13];
    const float* ln2b= (const float*)d_in[14];
    const float* Wg  = (const float*)d_in[15];
    const float* bg  = (const float*)d_in[16];
    const float* W1  = (const float*)d_in[17];
    const float* b1  = (const float*)d_in[18];
    const float* W2  = (const float*)d_in[19];
    const float* b2  = (const float*)d_in[20];
    float* out = (float*)d_out;

    float *p_qkvh, *p_tmp, *p_x, *p_y, *p_gates;
    __nv_bfloat16 *p_inhi, *p_xhi, *p_hhi;
    __nv_bfloat16 *p_w1h, *p_w2h, *p_wqkvh, *p_woh;
    cudaGetSymbolAddress((void**)&p_qkvh, d_qkvh);
    cudaGetSymbolAddress((void**)&p_tmp,  d_tmp);
    cudaGetSymbolAddress((void**)&p_x,    d_x);
    cudaGetSymbolAddress((void**)&p_y,    d_y);
    cudaGetSymbolAddress((void**)&p_gates,d_gates);
    cudaGetSymbolAddress((void**)&p_inhi, d_inhi);
    cudaGetSymbolAddress((void**)&p_xhi,  d_xhi);
    cudaGetSymbolAddress((void**)&p_hhi,  d_hhi);
    cudaGetSymbolAddress((void**)&p_w1h,  d_w1t_hi);
    cudaGetSymbolAddress((void**)&p_w2h,  d_w2t_hi);
    cudaGetSymbolAddress((void**)&p_wqkvh, d_wqkvt_hi);
    cudaGetSymbolAddress((void**)&p_woh,  d_wot_hi);

    static EncFn enc = nullptr;
    static cudaStream_t s2 = nullptr;
    static cudaEvent_t evFork = nullptr, evJoin = nullptr;
    if (!enc) {
        void* fp = nullptr;
        cudaDriverEntryPointQueryResult st;
        cudaGetDriverEntryPointByVersion("cuTensorMapEncodeTiled", &fp, 12000,
                                         cudaEnableDefault, &st);
        enc = (EncFn)fp;
        cudaStreamCreateWithFlags(&s2, cudaStreamNonBlocking);
        cudaEventCreateWithFlags(&evFork, cudaEventDisableTiming);
        cudaEventCreateWithFlags(&evJoin, cudaEventDisableTiming);
    }
    CUtensorMap mXh, mHh, mW1h, mW2h;
    make_map(enc, &mXh, p_xhi, Dq, MPAD, 1);
    make_map(enc, &mHh, p_hhi, Fq, MPAD, Eq);
    make_map(enc, &mW1h, p_w1h, Dq, Fq, Eq);
    make_map(enc, &mW2h, p_w2h, Fq, Dq, Eq);

    const dim3 blk(256);
    const dim3 gridQKV(Dq / TN, NTOK / TM, 3);
    const dim3 gridO(Dq / TN, NTOK / TM, 1);
    const dim3 grid1(Fq / 256, MPAD / 256, Eq);
    const dim3 grid2(Dq / 256, MPAD / 256, Eq);
    const int n4 = NTOK * Dq / 4;
    const int sgrid = (n4 + 255) / 256;
    const size_t segQ = (size_t)NTOK * Dq;

    cudaFuncSetAttribute(tc_gemm<2>,  cudaFuncAttributeMaxDynamicSharedMemorySize, TC_SMEM);
    cudaFuncSetAttribute(tc_gemm<3>,  cudaFuncAttributeMaxDynamicSharedMemorySize, TC_SMEM);
    cudaFuncSetAttribute(tc_gemm2<0>, cudaFuncAttributeMaxDynamicSharedMemorySize, TC2_SMEM);
    cudaFuncSetAttribute(tc_gemm2<1>, cudaFuncAttributeMaxDynamicSharedMemorySize, TC2_SMEM);
    cudaFuncSetAttribute(attn_kernel, cudaFuncAttributeMaxDynamicSharedMemorySize, ATT_SMEM);

    __nv_bfloat16* p_qkvshi = p_hhi;   // qkv-hi staging in idle h region

    // --- fork: W1/W2 transposes on s2, joined before GEMM1 ---
    cudaEventRecord(evFork, 0);
    cudaStreamWaitEvent(s2, evFork, 0);
    transpose_split<<<dim3(Dq/64, Fq/32, Eq), blk, 0, s2>>>(W1, p_w1h, Dq, Fq);
    transpose_split<<<dim3(Fq/64, Dq/32, Eq), blk, 0, s2>>>(W2, p_w2h, Fq, Dq);
    cudaEventRecord(evJoin, s2);

    // --- main chain ---
    transpose_split<<<dim3(Dq/64, Dq/32, 1), blk>>>(Wq, p_wqkvh,           Dq, Dq);
    transpose_split<<<dim3(Dq/64, Dq/32, 1), blk>>>(Wk, p_wqkvh + Dq*Dq,   Dq, Dq);
    transpose_split<<<dim3(Dq/64, Dq/32, 1), blk>>>(Wv, p_wqkvh + 2*Dq*Dq, Dq, Dq);
    split3_bf16<<<dim3(sgrid, 3), blk>>>(q, k, v, p_qkvshi, n4);
    tc_gemm<2><<<gridQKV, blk, TC_SMEM>>>(p_qkvshi, p_wqkvh,
                                          bq, bk, bv, nullptr, p_qkvh,
                                          NTOK, Dq, Dq, segQ, (size_t)Dq * Dq, segQ);
    attn_kernel<<<dim3(Bq * Hq, 4), blk, ATT_SMEM>>>(p_qkvh, p_qkvh + segQ, p_qkvh + 2 * segQ,
                                                     p_inhi);
    transpose_split<<<dim3(Dq/64, Dq/32, 1), blk>>>(Wo, p_woh, Dq, Dq);
    tc_gemm<3><<<gridO, blk, TC_SMEM>>>(p_inhi, p_woh,
                                        bo, bo, bo, q, p_tmp, NTOK, Dq, Dq, 0, 0, 0);
    ln_gate_kernel<<<NTOK, blk>>>(p_tmp, ln1g, ln1b, Wg, bg, p_x, p_xhi, p_gates);

    // --- join; MoE ---
    cudaStreamWaitEvent(0, evJoin, 0);
    tc_gemm2<0><<<grid1, blk, TC2_SMEM>>>(
        mXh, mW1h, b1, nullptr, p_hhi,
        Fq, Dq, (size_t)Fq, (size_t)MPAD * Fq,
        p_xhi, p_w1h, (size_t)0, (size_t)Fq * Dq);
    tc_gemm2<1><<<grid2, blk, TC2_SMEM>>>(
        mHh, mW2h, b2, p_y, nullptr,
        Dq, Fq, (size_t)Dq, (size_t)MPAD * Dq,
        p_hhi, p_w2h, (size_t)MPAD * Fq, (size_t)Dq * Fq);

    ln2_kernel<<<NTOK, blk>>>(p_x, p_y, p_gates, ln2g, ln2b, out);
}

// round 15
// speedup vs baseline: 12.7455x; 1.0629x over previous
#include <cuda_runtime.h>
#include <cuda.h>
#include <cuda_bf16.h>
#include <math.h>
#include <stdint.h>

#define Bq 32
#define Sq 196
#define Dq 768
#define Hq 12
#define Eq 8
#define Fq 3072
#define DHq 64
#define NTOK (Bq*Sq)
#define MPAD 6400

#define HAS_TCGEN05 (defined(__CUDA_ARCH_FEAT_SM103_ALL) || defined(__CUDA_ARCH_FEAT_SM100_ALL))

// ---------------- scratch ------------------------------------------------------
__device__ __align__(256) float d_qkvh[3*NTOK*Dq];
__device__ __align__(256) float d_tmp[NTOK*Dq];
__device__ __align__(256) float d_x  [NTOK*Dq];
__device__ __align__(256) float d_gates[MPAD*Eq];

__device__ __align__(256) __nv_bfloat16 d_yb [Eq*MPAD*Dq];  // gate-weighted expert outputs (bf16)
__device__ __align__(256) __nv_bfloat16 d_inhi[NTOK*Dq];    // ctx bf16
__device__ __align__(256) __nv_bfloat16 d_xhi[MPAD*Dq];
__device__ __align__(256) __nv_bfloat16 d_hhi[Eq*MPAD*Fq];  // h; also qkv-hi staging early
__device__ __align__(256) __nv_bfloat16 d_w1t_hi[Eq*Fq*Dq];
__device__ __align__(256) __nv_bfloat16 d_w2t_hi[Eq*Dq*Fq];
__device__ __align__(256) __nv_bfloat16 d_wqkvo[4*Dq*Dq];   // Wq|Wk|Wv|Wo transposed

// ---------------- PTX helpers ---------------------------------------------------
__device__ __forceinline__ uint32_t smem_u32(const void* p) {
    uint32_t a;
    asm("{ .reg .u64 t; cvta.to.shared.u64 t, %1; cvt.u32.u64 %0, t; }" : "=r"(a) : "l"(p));
    return a;
}

#if HAS_TCGEN05
__device__ __forceinline__ bool elect_one() {
    uint32_t p;
    asm volatile("{\n .reg .pred p;\n elect.sync _|p, 0xFFFFFFFF;\n selp.b32 %0,1,0,p;\n}" : "=r"(p));
    return p != 0;
}
#define MBARRIER_INIT(addr, cnt) \
    asm volatile("mbarrier.init.shared.b64 [%0], %1;" :: "r"((uint32_t)(addr)), "r"((uint32_t)(cnt)) : "memory")
#define MBARRIER_INVAL(addr) \
    asm volatile("mbarrier.inval.shared.b64 [%0];" :: "r"((uint32_t)(addr)) : "memory")
#define MBARRIER_EXPECT_TX(addr, tx) \
    asm volatile("mbarrier.arrive.expect_tx.shared.b64 _, [%0], %1;" \
        :: "r"((uint32_t)(addr)), "r"((uint32_t)(tx)) : "memory")
#define MBARRIER_WAIT_PARITY(mbar, par) do { \
    uint32_t _m = (uint32_t)(mbar), _p = (uint32_t)(par), _d; \
    asm volatile("{\n\t.reg .pred p;\n\t" \
        "mbarrier.try_wait.parity.acquire.cta.shared::cta.b64 p, [%1], %2;\n\t" \
        "selp.b32 %0, 1, 0, p;\n\t}" : "=r"(_d) : "r"(_m), "r"(_p) : "memory"); \
    if (!_d) { \
        asm volatile("{\n\t.reg .pred P1;\n\t" \
            "WL_%=:\n\t" \
            "mbarrier.try_wait.parity.acquire.cta.shared::cta.b64 P1, [%0], %1, 0x989680;\n\t" \
            "@P1 bra.uni WD_%=;\n\tbra.uni WL_%=;\n\tWD_%=:\n\t}" \
            :: "r"(_m), "r"(_p) : "memory"); \
    } \
} while(0)
#define TCGEN05_ALLOC(a, n) \
    asm volatile("tcgen05.alloc.cta_group::1.sync.aligned.shared::cta.b32 [%0], %1;" \
        :: "r"((uint32_t)(a)), "r"((uint32_t)(n)) : "memory")
#define TCGEN05_DEALLOC(t, n) \
    asm volatile("tcgen05.dealloc.cta_group::1.sync.aligned.b32 %0, %1;" :: "r"(t), "r"(n))
#define TCGEN05_RELINQ() \
    asm volatile("tcgen05.relinquish_alloc_permit.cta_group::1.sync.aligned;")
#define TCGEN05_COMMIT(m) \
    asm volatile("tcgen05.commit.cta_group::1.mbarrier::arrive::one.shared::cluster.b64 [%0];" \
        :: "r"((uint32_t)(m)) : "memory")
#define TCGEN05_FENCE_AFTER()  asm volatile("tcgen05.fence::after_thread_sync;" ::: "memory")
#define TCGEN05_FENCE_BEFORE() asm volatile("tcgen05.fence::before_thread_sync;" ::: "memory")
#define TCGEN05_WAIT_LD() asm volatile("tcgen05.wait::ld.sync.aligned;" ::: "memory")
#define FENCE_ASYNC_SHARED() asm volatile("fence.proxy.async.shared::cta;" ::: "memory")
#define CP_ASYNC16(dst, src) \
    asm volatile("cp.async.cg.shared.global [%0], [%1], 16;" :: "r"((uint32_t)(dst)), "l"(src))
#define CP_COMMIT() asm volatile("cp.async.commit_group;" ::: "memory")
#define CP_WAIT(n)  asm volatile("cp.async.wait_group %0;" :: "n"(n) : "memory")
#define TMA_LOAD_3D(sm, map, cx, cy, cz, mb) \
    asm volatile("cp.async.bulk.tensor.3d.shared::cta.global.tile.mbarrier::complete_tx::bytes " \
        "[%0], [%1, {%2, %3, %4}], [%5];" \
        :: "r"((uint32_t)(sm)), "l"(map), "r"((int32_t)(cx)), "r"((int32_t)(cy)), \
           "r"((int32_t)(cz)), "r"((uint32_t)(mb)) : "memory")
#define TCGEN05_LD_32X32B_X32(r, ta) \
    asm volatile("tcgen05.ld.sync.aligned.32x32b.x32.b32 " \
        "{%0, %1, %2, %3, %4, %5, %6, %7, %8, %9, %10, %11, %12, %13, %14, %15, " \
        " %16, %17, %18, %19, %20, %21, %22, %23, %24, %25, %26, %27, %28, %29, %30, %31}, [%32];" \
        : "=r"((r)[0]), "=r"((r)[1]), "=r"((r)[2]), "=r"((r)[3]), "=r"((r)[4]), "=r"((r)[5]), \
          "=r"((r)[6]), "=r"((r)[7]), "=r"((r)[8]), "=r"((r)[9]), "=r"((r)[10]), "=r"((r)[11]), \
          "=r"((r)[12]), "=r"((r)[13]), "=r"((r)[14]), "=r"((r)[15]), "=r"((r)[16]), "=r"((r)[17]), \
          "=r"((r)[18]), "=r"((r)[19]), "=r"((r)[20]), "=r"((r)[21]), "=r"((r)[22]), "=r"((r)[23]), \
          "=r"((r)[24]), "=r"((r)[25]), "=r"((r)[26]), "=r"((r)[27]), "=r"((r)[28]), "=r"((r)[29]), \
          "=r"((r)[30]), "=r"((r)[31]) : "r"(ta))

static constexpr uint64_t DESC_SW128 =
    (uint64_t(2) << 61) | (uint64_t(1) << 46) | (uint64_t(64) << 32) | (uint64_t(1) << 16);
static constexpr uint64_t DESC_SW64 =
    (uint64_t(4) << 61) | (uint64_t(1) << 46) | (uint64_t(32) << 32) | (uint64_t(1) << 16);
#define MKD128(a) (DESC_SW128 | ((uint64_t)((a) >> 4) & 0x3FFF))
#define MKD64(a)  (DESC_SW64  | ((uint64_t)((a) >> 4) & 0x3FFF))

__device__ __forceinline__ void mma_bf16_ss(uint32_t d, uint64_t ad, uint64_t bd,
                                            uint32_t idesc, uint32_t en) {
    asm volatile(
        "{\n\t.reg .pred p;\n\tsetp.ne.u32 p, %5, 0;\n\t"
        "tcgen05.mma.cta_group::1.kind::f16 [%0], %1, %2, %3, {%4,%4,%4,%4}, p;\n\t}"
        :: "r"(d), "l"(ad), "l"(bd), "r"(idesc), "r"(0u), "r"(en) : "memory");
}
static constexpr uint32_t IDESC_BF16 =
    (1u << 4) | (1u << 7) | (1u << 10) | ((256 / 8) << 17) | ((128 / 16) << 24);
#endif

// ======================= TM128 tc GEMM (QKV batched / O-proj, pure bf16) ========
#define TM 128
#define TN 256
#define TK 64
#define STG128 49152
#define SM_DATA 1024
#define TC_SMEM (SM_DATA + 2*STG128)

#if HAS_TCGEN05
__device__ __forceinline__ void load_slab128(
    uint32_t sbase, int stage,
    const __nv_bfloat16* __restrict__ A, const __nv_bfloat16* __restrict__ B,
    int m0, int n0, int k0, int K)
{
    const int tid = threadIdx.x;
    const uint32_t base = sbase + SM_DATA + stage * STG128;
#pragma unroll
    for (int i = 0; i < 4; i++) {
        int idx = i * 256 + tid;
        int row = idx >> 3, c4 = idx & 7;
        int off = row * 128 + c4 * 16;
        int sw  = off ^ ((off >> 3) & 0x70);
        size_t g = (size_t)(m0 + row) * K + k0 + c4 * 8;
        CP_ASYNC16(base + sw, A + g);
    }
#pragma unroll
    for (int i = 0; i < 8; i++) {
        int idx = i * 256 + tid;
        int row = idx >> 3, c4 = idx & 7;
        int off = row * 128 + c4 * 16;
        int sw  = off ^ ((off >> 3) & 0x70);
        size_t g = (size_t)(n0 + row) * K + k0 + c4 * 8;
        CP_ASYNC16(base + 16384 + sw, B + g);
    }
    CP_COMMIT();
}
#endif

template<int MODE>   // 2: z-batched C=AW+b(z)   3: C=AW+b+res
__global__ void __launch_bounds__(256)
tc_gemm(const __nv_bfloat16* __restrict__ A, const __nv_bfloat16* __restrict__ B,
        const float* __restrict__ b0, const float* __restrict__ b1,
        const float* __restrict__ b2, const float* __restrict__ res,
        float* __restrict__ Cf, int M, int N, int K,
        size_t sA, size_t sB, size_t sC)
{
    extern __shared__ __align__(1024) char smx[];
    const int z = blockIdx.z;
    A += z * sA; B += z * sB;
    Cf += z * sC;
    const float* bias = (z == 0) ? b0 : (z == 1) ? b1 : b2;
#if HAS_TCGEN05
    const uint32_t sb = smem_u32(smx);
    const int tid = threadIdx.x;
    const int wid = tid >> 5, lane = tid & 31;
    const int m0 = blockIdx.y * TM, n0 = blockIdx.x * TN;

    if (wid == 0) { TCGEN05_ALLOC(sb, 256); TCGEN05_RELINQ(); }
    if (tid == 0) { MBARRIER_INIT(sb + 8, 1); MBARRIER_INIT(sb + 16, 1); }
    __syncthreads();
    uint32_t tmem;
    asm volatile("ld.shared.b32 %0, [%1];" : "=r"(tmem) : "r"(sb));

    const int NS = K / TK;
    load_slab128(sb, 0, A, B, m0, n0, 0, K);
    int ph0 = 0, ph1 = 0;
    for (int s = 0; s < NS; s++) {
        const int buf = s & 1;
        if (s + 1 < NS) {
            const int nb = 1 - buf;
            if (s >= 1) {
                if (nb == 0) { MBARRIER_WAIT_PARITY(sb + 8,  ph0); ph0 ^= 1; }
                else         { MBARRIER_WAIT_PARITY(sb + 16, ph1); ph1 ^= 1; }
            }
            load_slab128(sb, nb, A, B, m0, n0, (s + 1) * TK, K);
            CP_WAIT(1);
        } else {
            CP_WAIT(0);
        }
        FENCE_ASYNC_SHARED();
        __syncthreads();
        if (wid == 0) {
            TCGEN05_FENCE_AFTER();
            if (elect_one()) {
                const uint32_t tb = sb + SM_DATA + buf * STG128;
                const uint64_t ah = MKD128(tb);
                const uint64_t bh = MKD128(tb + 16384);
#pragma unroll
                for (int ks = 0; ks < 4; ks++) {
                    const uint32_t en0 = (s == 0 && ks == 0) ? 0u : 1u;
                    mma_bf16_ss(tmem, ah + ks * 2, bh + ks * 2, IDESC_BF16, en0);
                }
                TCGEN05_COMMIT(sb + 8 + buf * 8);
            }
        }
    }
    if (((NS - 1) & 1) == 0) { MBARRIER_WAIT_PARITY(sb + 8,  ph0); }
    else                     { MBARRIER_WAIT_PARITY(sb + 16, ph1); }
    TCGEN05_FENCE_AFTER();

    const int sub = wid & 3, cg = wid >> 2;
    const int row = m0 + sub * 32 + lane;
#pragma unroll
    for (int ch = 0; ch < 4; ch++) {
        const int colb = cg * 128 + ch * 32;
        uint32_t r[32];
        TCGEN05_LD_32X32B_X32(r, tmem + colb);
        TCGEN05_WAIT_LD();
        const size_t base = (size_t)row * N + n0 + colb;
        const float4* bv = (const float4*)(bias + n0 + colb);
        float4* dst = (float4*)(Cf + base);
        const float4* rv = (MODE == 3) ? (const float4*)(res + base) : nullptr;
#pragma unroll
        for (int i = 0; i < 8; i++) {
            float4 b4 = bv[i];
            float4 o;
            o.x = __uint_as_float(r[i*4+0]) + b4.x;
            o.y = __uint_as_float(r[i*4+1]) + b4.y;
            o.z = __uint_as_float(r[i*4+2]) + b4.z;
            o.w = __uint_as_float(r[i*4+3]) + b4.w;
            if (MODE == 3) { float4 t = rv[i]; o.x += t.x; o.y += t.y; o.z += t.z; o.w += t.w; }
            dst[i] = o;
        }
    }
    TCGEN05_FENCE_BEFORE();
    __syncthreads();
    if (tid == 0) { MBARRIER_INVAL(sb + 8); MBARRIER_INVAL(sb + 16); }
    __syncthreads();
    if (wid == 0) TCGEN05_DEALLOC(tmem, 256);
#else
    float* As = (float*)smx;
    float* Bs = As + 16 * 128;
    const int tid = threadIdx.x;
    const int m0 = blockIdx.y * TM, n0x = blockIdx.x * TN;
    const int tx = tid & 15, ty = tid >> 4;
    const int mr = ty * 8, nr = tx * 8;
    for (int half = 0; half < 2; half++) {
        const int n0 = n0x + half * 128;
        float acc[8][8];
#pragma unroll
        for (int i = 0; i < 8; i++)
#pragma unroll
            for (int j = 0; j < 8; j++) acc[i][j] = 0.f;
        for (int k0 = 0; k0 < K; k0 += 16) {
            __syncthreads();
#pragma unroll
            for (int i = 0; i < 8; i++) {
                int idx = i * 256 + tid;
                int kk = idx >> 7, mm = idx & 127;
                size_t ga = (size_t)(m0 + mm) * K + k0 + kk;
                size_t gb = (size_t)(n0 + mm) * K + k0 + kk;
                As[kk*128+mm] = __bfloat162float(A[ga]);
                Bs[kk*128+mm] = __bfloat162float(B[gb]);
            }
            __syncthreads();
#pragma unroll
            for (int kk = 0; kk < 16; kk++) {
                float a0[8], b0r[8];
#pragma unroll
                for (int i = 0; i < 8; i++) a0[i] = As[kk*128+mr+i];
#pragma unroll
                for (int j = 0; j < 8; j++) b0r[j] = Bs[kk*128+nr+j];
#pragma unroll
                for (int i = 0; i < 8; i++)
#pragma unroll
                    for (int j = 0; j < 8; j++)
                        acc[i][j] = fmaf(a0[i], b0r[j], acc[i][j]);
            }
        }
#pragma unroll
        for (int i = 0; i < 8; i++) {
            const int row = m0 + mr + i;
#pragma unroll
            for (int j = 0; j < 8; j++) {
                const int col = n0 + nr + j;
                const size_t idx = (size_t)row * N + col;
                float v = acc[i][j] + bias[col];
                if (MODE == 2) Cf[idx] = v; else Cf[idx] = v + res[idx];
            }
        }
    }
#endif
}

// ======================= MoE GEMM: pure bf16, TMA producer/consumer =============
// MODE 0: gelu(acc+bias)->bf16 h      MODE 1: gate*(acc+bias)->bf16 y
#define T2K 32
#define SLAB2 32768
#define TC2_SMEM (1024 + 6*SLAB2)

template<int MODE>
__global__ void __launch_bounds__(256)
tc_gemm2(const __grid_constant__ CUtensorMap mA, const __grid_constant__ CUtensorMap mB,
         const float* __restrict__ bias, const float* __restrict__ gates,
         __nv_bfloat16* __restrict__ Chi,
         int N, int K, size_t sBias, size_t sC,
         const __nv_bfloat16* __restrict__ A, const __nv_bfloat16* __restrict__ B,
         size_t sA, size_t sB)
{
    extern __shared__ __align__(1024) char smx[];
    const int z = blockIdx.z;
    bias += z * sBias;
    Chi += z * sC;
#if HAS_TCGEN05
    const uint32_t sb = smem_u32(smx);
    const int tid = threadIdx.x;
    const int wid = tid >> 5, lane = tid & 31;
    const int m0 = blockIdx.y * 256, n0 = blockIdx.x * 256;
    const int za = (MODE == 0) ? 0 : z;

    if (wid == 0) { TCGEN05_ALLOC(sb, 512); TCGEN05_RELINQ(); }
    if (tid == 0) {
#pragma unroll
        for (int i = 0; i < 6; i++) { MBARRIER_INIT(sb + 8 + i * 8, 1); MBARRIER_INIT(sb + 56 + i * 8, 1); }
        MBARRIER_INIT(sb + 104, 1);
        FENCE_ASYNC_SHARED();
    }
    __syncthreads();
    uint32_t tmem;
    asm volatile("ld.shared.b32 %0, [%1];" : "=r"(tmem) : "r"(sb));

    const int NS = K / T2K;
    if (wid == 1) {
        if (elect_one()) {
            for (int s = 0; s < NS; s++) {
                const int st = s % 6;
                if (s >= 6) MBARRIER_WAIT_PARITY(sb + 56 + st * 8, ((s / 6) - 1) & 1);
                MBARRIER_EXPECT_TX(sb + 8 + st * 8, (uint32_t)SLAB2);
                const uint32_t stb = sb + 1024 + st * SLAB2;
                const int k0 = s * T2K;
                TMA_LOAD_3D(stb,         &mA, k0, m0, za, sb + 8 + st * 8);
                TMA_LOAD_3D(stb + 16384, &mB, k0, n0, z,  sb + 8 + st * 8);
            }
        }
    } else if (wid == 0) {
        TCGEN05_FENCE_AFTER();
        if (elect_one()) {
            for (int s = 0; s < NS; s++) {
                const int st = s % 6;
                MBARRIER_WAIT_PARITY(sb + 8 + st * 8, (s / 6) & 1);
                const uint32_t tb = sb + 1024 + st * SLAB2;
                const uint64_t a0 = MKD64(tb);
                const uint64_t a1 = a0 + 512;
                const uint64_t bh = MKD64(tb + 16384);
#pragma unroll
                for (int ks = 0; ks < 2; ks++) {
                    const uint32_t en0 = (s == 0 && ks == 0) ? 0u : 1u;
                    mma_bf16_ss(tmem,       a0 + ks * 2, bh + ks * 2, IDESC_BF16, en0);
                    mma_bf16_ss(tmem + 256, a1 + ks * 2, bh + ks * 2, IDESC_BF16, en0);
                }
                TCGEN05_COMMIT(sb + 56 + st * 8);
            }
            TCGEN05_COMMIT(sb + 104);
        }
    }

    MBARRIER_WAIT_PARITY(sb + 104, 0);
    TCGEN05_FENCE_AFTER();

    const int accSel = wid >> 2, sub = wid & 3;
    const int row = m0 + accSel * 128 + sub * 32 + lane;
    const uint32_t tacc = tmem + accSel * 256;
    const float gate = (MODE == 1) ? gates[(size_t)row * Eq + z] : 0.f;
#pragma unroll
    for (int ch = 0; ch < 8; ch++) {
        const int colb = ch * 32;
        uint32_t r[32];
        TCGEN05_LD_32X32B_X32(r, tacc + colb);
        TCGEN05_WAIT_LD();
        const size_t base = (size_t)row * N + n0 + colb;
        const float4* bv = (const float4*)(bias + n0 + colb);
        uint4* dh = (uint4*)(Chi + base);
#pragma unroll
        for (int i = 0; i < 4; i++) {
            uint32_t hp[4];
#pragma unroll
            for (int p = 0; p < 4; p++) {
                float4 b4 = bv[i * 2 + (p >> 1)];
                float b0 = (p & 1) ? b4.z : b4.x;
                float b1 = (p & 1) ? b4.w : b4.y;
                float v0 = __uint_as_float(r[i*8+p*2+0]) + b0;
                float v1 = __uint_as_float(r[i*8+p*2+1]) + b1;
                float g0, g1;
                if (MODE == 0) {
                    g0 = 0.5f * v0 * (1.f + erff(v0 * 0.70710678118654752f));
                    g1 = 0.5f * v1 * (1.f + erff(v1 * 0.70710678118654752f));
                } else {
                    g0 = v0 * gate;
                    g1 = v1 * gate;
                }
                hp[p] = (uint32_t)__bfloat16_as_ushort(__float2bfloat16(g0)) |
                        ((uint32_t)__bfloat16_as_ushort(__float2bfloat16(g1)) << 16);
            }
            dh[i] = make_uint4(hp[0], hp[1], hp[2], hp[3]);
        }
    }
    TCGEN05_FENCE_BEFORE();
    __syncthreads();
    if (tid == 0) {
#pragma unroll
        for (int i = 0; i < 6; i++) { MBARRIER_INVAL(sb + 8 + i * 8); MBARRIER_INVAL(sb + 56 + i * 8); }
        MBARRIER_INVAL(sb + 104);
    }
    __syncthreads();
    if (wid == 0) TCGEN05_DEALLOC(tmem, 512);
#else
    const __nv_bfloat16* Ap = A + (size_t)((MODE == 0) ? 0 : z) * sA;
    const __nv_bfloat16* Bp = B + (size_t)z * sB;
    float* As = (float*)smx;
    float* Bs = As + 16 * 128;
    const int tid = threadIdx.x;
    const int tx = tid & 15, ty = tid >> 4;
    const int mr = ty * 8, nr = tx * 8;
    for (int mh = 0; mh < 2; mh++)
    for (int nh = 0; nh < 2; nh++) {
        const int m0 = blockIdx.y * 256 + mh * 128;
        const int n0 = blockIdx.x * 256 + nh * 128;
        float acc[8][8];
#pragma unroll
        for (int i = 0; i < 8; i++)
#pragma unroll
            for (int j = 0; j < 8; j++) acc[i][j] = 0.f;
        for (int k0 = 0; k0 < K; k0 += 16) {
            __syncthreads();
#pragma unroll
            for (int i = 0; i < 8; i++) {
                int idx = i * 256 + tid;
                int kk = idx >> 7, mm = idx & 127;
                size_t ga = (size_t)(m0 + mm) * K + k0 + kk;
                size_t gb = (size_t)(n0 + mm) * K + k0 + kk;
                As[kk*128+mm] = __bfloat162float(Ap[ga]);
                Bs[kk*128+mm] = __bfloat162float(Bp[gb]);
            }
            __syncthreads();
#pragma unroll
            for (int kk = 0; kk < 16; kk++) {
                float a0[8], b0[8];
#pragma unroll
                for (int i = 0; i < 8; i++) a0[i] = As[kk*128+mr+i];
#pragma unroll
                for (int j = 0; j < 8; j++) b0[j] = Bs[kk*128+nr+j];
#pragma unroll
                for (int i = 0; i < 8; i++)
#pragma unroll
                    for (int j = 0; j < 8; j++)
                        acc[i][j] = fmaf(a0[i], b0[j], acc[i][j]);
            }
        }
#pragma unroll
        for (int i = 0; i < 8; i++) {
            const int row = m0 + mr + i;
            const float gate = (MODE == 1) ? gates[(size_t)row * Eq + z] : 0.f;
#pragma unroll
            for (int j = 0; j < 8; j++) {
                const int col = n0 + nr + j;
                const size_t idx = (size_t)row * N + col;
                float v = acc[i][j] + bias[col];
                if (MODE == 0) {
                    float g = 0.5f * v * (1.f + erff(v * 0.70710678118654752f));
                    Chi[idx] = __float2bfloat16(g);
                } else {
                    Chi[idx] = __float2bfloat16(v * gate);
                }
            }
        }
    }
#endif
}

// ---------------- transpose: batched Wq/Wk/Wv/Wo (all D x D) ------------------------
__global__ void __launch_bounds__(256)
transpose_qkvo(const float* __restrict__ W0, const float* __restrict__ W1p,
               const float* __restrict__ W2p, const float* __restrict__ W3p,
               __nv_bfloat16* __restrict__ T)
{
    __shared__ float t[64][33];
    const int z = blockIdx.z;
    const float* Wp = (z == 0) ? W0 : (z == 1) ? W1p : (z == 2) ? W2p : W3p;
    __nv_bfloat16* th = T + (size_t)z * Dq * Dq;
    const int k0 = blockIdx.x * 64, n0 = blockIdx.y * 32;
    const int tid = threadIdx.x;
#pragma unroll
    for (int i = 0; i < 8; i++) {
        int idx = i * 256 + tid;
        int r = idx >> 5, c = idx & 31;
        t[r][c] = Wp[(size_t)(k0 + r) * Dq + n0 + c];
    }
    __syncthreads();
#pragma unroll
    for (int i = 0; i < 4; i++) {
        int idx = i * 256 + tid;
        int c = idx >> 5, j = idx & 31;
        float v0 = t[2 * j][c], v1 = t[2 * j + 1][c];
        __nv_bfloat16 h0 = __float2bfloat16(v0);
        __nv_bfloat16 h1 = __float2bfloat16(v1);
        const size_t base = (size_t)(n0 + c) * Dq + k0 + 2 * j;
        *(uint32_t*)(th + base) =
            (uint32_t)__bfloat16_as_ushort(h0) | ((uint32_t)__bfloat16_as_ushort(h1) << 16);
    }
}

// ---------------- transpose (expert weights, hi only) -------------------------------
__global__ void __launch_bounds__(256)
transpose_split(const float* __restrict__ W, __nv_bfloat16* __restrict__ Thi,
                int K, int N)
{
    __shared__ float t[64][33];
    const int e = blockIdx.z;
    const float* Wp = W + (size_t)e * K * N;
    __nv_bfloat16* th = Thi + (size_t)e * K * N;
    const int k0 = blockIdx.x * 64, n0 = blockIdx.y * 32;
    const int tid = threadIdx.x;
#pragma unroll
    for (int i = 0; i < 8; i++) {
        int idx = i * 256 + tid;
        int r = idx >> 5, c = idx & 31;
        t[r][c] = Wp[(size_t)(k0 + r) * N + n0 + c];
    }
    __syncthreads();
#pragma unroll
    for (int i = 0; i < 4; i++) {
        int idx = i * 256 + tid;
        int c = idx >> 5, j = idx & 31;
        float v0 = t[2 * j][c], v1 = t[2 * j + 1][c];
        __nv_bfloat16 h0 = __float2bfloat16(v0);
        __nv_bfloat16 h1 = __float2bfloat16(v1);
        const size_t base = (size_t)(n0 + c) * K + k0 + 2 * j;
        *(uint32_t*)(th + base) =
            (uint32_t)__bfloat16_as_ushort(h0) | ((uint32_t)__bfloat16_as_ushort(h1) << 16);
    }
}

// ---------------- batched q/k/v -> bf16 (hi only) --------------------------------------
__global__ void __launch_bounds__(256)
split3_bf16(const float* __restrict__ q, const float* __restrict__ k,
            const float* __restrict__ v, __nv_bfloat16* __restrict__ hi, int n4)
{
    const int seg = blockIdx.y;
    const float* x = (seg == 0) ? q : (seg == 1) ? k : v;
    int i = blockIdx.x * 256 + threadIdx.x;
    if (i >= n4) return;
    float4 val = ((const float4*)x)[i];
    __nv_bfloat16 h0 = __float2bfloat16(val.x), h1 = __float2bfloat16(val.y);
    __nv_bfloat16 h2 = __float2bfloat16(val.z), h3 = __float2bfloat16(val.w);
    uint2 hp;
    hp.x = (uint32_t)__bfloat16_as_ushort(h0) | ((uint32_t)__bfloat16_as_ushort(h1) << 16);
    hp.y = (uint32_t)__bfloat16_as_ushort(h2) | ((uint32_t)__bfloat16_as_ushort(h3) << 16);
    ((uint2*)hi)[(size_t)seg * n4 + i] = hp;
}

// ---------------- attention v4: emits bf16 ctx (hi only) ------------------------------
#define ATT_V 28224
#define ATT_Q 78400
#define ATT_P 86592
#define ATT_SMEM 112192

__global__ void __launch_bounds__(256, 2)
attn_kernel(const float* __restrict__ qh, const float* __restrict__ kh,
            const float* __restrict__ vh, __nv_bfloat16* __restrict__ chi)
{
    const int b = blockIdx.x / Hq;
    const int h = blockIdx.x % Hq;
    const int qbase = blockIdx.y * 49;
    const int qend  = min(196, qbase + 49);
    extern __shared__ __align__(16) char sm[];
    uint32_t* Ksp = (uint32_t*)sm;
    float* Vs = (float*)(sm + ATT_V);
    float* Qs = (float*)(sm + ATT_Q);
    float* Ps = (float*)(sm + ATT_P);
    const int tid = threadIdx.x;

    for (int i = tid; i < Sq * 32; i += 256) {
        int s = i >> 5, dp = i & 31;
        size_t g = (size_t)(b * Sq + s) * Dq + h * DHq + 2 * dp;
        float2 kv = *(const float2*)(kh + g);
        __nv_bfloat16 k0 = __float2bfloat16(kv.x), k1 = __float2bfloat16(kv.y);
        Ksp[s * 36 + dp] = (uint32_t)__bfloat16_as_ushort(k0) |
                           ((uint32_t)__bfloat16_as_ushort(k1) << 16);
        *(float2*)(Vs + s * 64 + 2 * dp) = *(const float2*)(vh + g);
    }
    __syncthreads();

    const int warp = tid >> 5, lane = tid & 31;
    float* Qw = Qs + warp * 256;
    float* Pw = Ps + warp * 800;

    for (int q0 = qbase + warp * 4; q0 < qend; q0 += 32) {
        const int nq = min(4, qend - q0);
#pragma unroll
        for (int qq = 0; qq < 4; qq++) {
            int qi = q0 + qq;
#pragma unroll
            for (int r = 0; r < 2; r++) {
                int d = lane + r * 32;
                Qw[qq * 64 + d] = (qi < qend) ?
                    qh[(size_t)(b * Sq + qi) * Dq + h * DHq + d] : 0.f;
            }
        }
        __syncwarp();

        float s4[4][7];
#pragma unroll
        for (int qq = 0; qq < 4; qq++)
#pragma unroll
            for (int c = 0; c < 7; c++) s4[qq][c] = 0.f;
#pragma unroll
        for (int d8 = 0; d8 < 8; d8++) {
            float qv[4][8];
#pragma unroll
            for (int qq = 0; qq < 4; qq++) {
                float4 a = *(float4*)(Qw + qq * 64 + d8 * 8);
                float4 bb = *(float4*)(Qw + qq * 64 + d8 * 8 + 4);
                qv[qq][0] = a.x;  qv[qq][1] = a.y;  qv[qq][2] = a.z;  qv[qq][3] = a.w;
                qv[qq][4] = bb.x; qv[qq][5] = bb.y; qv[qq][6] = bb.z; qv[qq][7] = bb.w;
            }
#pragma unroll
            for (int c = 0; c < 7; c++) {
                int col = lane + 32 * c;
                if (col < Sq) {
                    uint4 kp = *(uint4*)(Ksp + col * 36 + d8 * 4);
                    float kf[8];
                    kf[0] = __uint_as_float(kp.x << 16);
                    kf[1] = __uint_as_float(kp.x & 0xFFFF0000u);
                    kf[2] = __uint_as_float(kp.y << 16);
                    kf[3] = __uint_as_float(kp.y & 0xFFFF0000u);
                    kf[4] = __uint_as_float(kp.z << 16);
                    kf[5] = __uint_as_float(kp.z & 0xFFFF0000u);
                    kf[6] = __uint_as_float(kp.w << 16);
                    kf[7] = __uint_as_float(kp.w & 0xFFFF0000u);
#pragma unroll
                    for (int qq = 0; qq < 4; qq++) {
                        float s = s4[qq][c];
#pragma unroll
                        for (int e = 0; e < 8; e++) s = fmaf(kf[e], qv[qq][e], s);
                        s4[qq][c] = s;
                    }
                }
            }
        }

        float inv[4];
#pragma unroll
        for (int qq = 0; qq < 4; qq++) {
            float m = -1e30f;
#pragma unroll
            for (int c = 0; c < 7; c++) {
                int col = lane + 32 * c;
                if (col < Sq) m = fmaxf(m, s4[qq][c] * 0.125f);
            }
#pragma unroll
            for (int o = 16; o; o >>= 1) m = fmaxf(m, __shfl_xor_sync(0xffffffffu, m, o));
            float sum = 0.f;
#pragma unroll
            for (int c = 0; c < 7; c++) {
                int col = lane + 32 * c;
                if (col < Sq) {
                    float e = __expf(s4[qq][c] * 0.125f - m);
                    Pw[qq * 200 + col] = e;
                    sum += e;
                }
            }
#pragma unroll
            for (int o = 16; o; o >>= 1) sum += __shfl_xor_sync(0xffffffffu, sum, o);
            inv[qq] = 1.f / sum;
        }
        __syncwarp();

        float acc[4][2];
#pragma unroll
        for (int qq = 0; qq < 4; qq++) { acc[qq][0] = 0.f; acc[qq][1] = 0.f; }
        for (int k4 = 0; k4 < Sq; k4 += 4) {
            float pa[4][4];
#pragma unroll
            for (int qq = 0; qq < 4; qq++) {
                float4 p = *(float4*)(Pw + qq * 200 + k4);
                pa[qq][0] = p.x; pa[qq][1] = p.y; pa[qq][2] = p.z; pa[qq][3] = p.w;
            }
#pragma unroll
            for (int j = 0; j < 4; j++) {
                float2 vv = *(float2*)(Vs + (k4 + j) * 64 + 2 * lane);
#pragma unroll
                for (int qq = 0; qq < 4; qq++) {
                    acc[qq][0] = fmaf(pa[qq][j], vv.x, acc[qq][0]);
                    acc[qq][1] = fmaf(pa[qq][j], vv.y, acc[qq][1]);
                }
            }
        }
#pragma unroll
        for (int qq = 0; qq < 4; qq++) {
            if (qq < nq) {
                float ox = acc[qq][0] * inv[qq];
                float oy = acc[qq][1] * inv[qq];
                __nv_bfloat16 h0 = __float2bfloat16(ox);
                __nv_bfloat16 h1 = __float2bfloat16(oy);
                const size_t idx = (size_t)(b * Sq + q0 + qq) * Dq + h * DHq + 2 * lane;
                *(uint32_t*)(chi + idx) =
                    (uint32_t)__bfloat16_as_ushort(h0) | ((uint32_t)__bfloat16_as_ushort(h1) << 16);
            }
        }
        __syncwarp();
    }
}

// ---------------- LN1 + gate fused ---------------------------------------------------
__global__ void __launch_bounds__(256)
ln_gate_kernel(const float* __restrict__ a, const float* __restrict__ g,
               const float* __restrict__ be, const float* __restrict__ Wg,
               const float* __restrict__ bg, float* __restrict__ out,
               __nv_bfloat16* __restrict__ ohi, float* __restrict__ gates)
{
    const int row = blockIdx.x;
    const float* ar = a + (size_t)row * Dq;
    float v[3];
    float s = 0.f, s2 = 0.f;
#pragma unroll
    for (int i = 0; i < 3; i++) {
        int d = threadIdx.x + i * 256;
        float x = ar[d];
        v[i] = x;
        s += x; s2 = fmaf(x, x, s2);
    }
    __shared__ float rs[8], rs2[8];
#pragma unroll
    for (int o = 16; o; o >>= 1) { s += __shfl_xor_sync(0xffffffffu, s, o); s2 += __shfl_xor_sync(0xffffffffu, s2, o); }
    const int warp = threadIdx.x >> 5, lane = threadIdx.x & 31;
    if (lane == 0) { rs[warp] = s; rs2[warp] = s2; }
    __syncthreads();
    if (warp == 0) {
        float t  = (lane < 8) ? rs[lane]  : 0.f;
        float t2 = (lane < 8) ? rs2[lane] : 0.f;
#pragma unroll
        for (int o = 4; o; o >>= 1) { t += __shfl_xor_sync(0xffffffffu, t, o); t2 += __shfl_xor_sync(0xffffffffu, t2, o); }
        if (lane == 0) { rs[0] = t; rs2[0] = t2; }
    }
    __syncthreads();
    const float mu  = rs[0] * (1.f / Dq);
    const float var = rs2[0] * (1.f / Dq) - mu * mu;
    const float inv = rsqrtf(var + 1e-5f);

    float lg[Eq];
#pragma unroll
    for (int e = 0; e < Eq; e++) lg[e] = 0.f;
#pragma unroll
    for (int i = 0; i < 3; i++) {
        int d = threadIdx.x + i * 256;
        float y = (v[i] - mu) * inv * g[d] + be[d];
        const size_t idx = (size_t)row * Dq + d;
        out[idx] = y;
        ohi[idx] = __float2bfloat16(y);
        const float4* wg4 = (const float4*)(Wg + (size_t)d * Eq);
        float4 w0 = wg4[0], w1 = wg4[1];
        lg[0] = fmaf(y, w0.x, lg[0]); lg[1] = fmaf(y, w0.y, lg[1]);
        lg[2] = fmaf(y, w0.z, lg[2]); lg[3] = fmaf(y, w0.w, lg[3]);
        lg[4] = fmaf(y, w1.x, lg[4]); lg[5] = fmaf(y, w1.y, lg[5]);
        lg[6] = fmaf(y, w1.z, lg[6]); lg[7] = fmaf(y, w1.w, lg[7]);
    }
#pragma unroll
    for (int e = 0; e < Eq; e++)
#pragma unroll
        for (int o = 16; o; o >>= 1) lg[e] += __shfl_xor_sync(0xffffffffu, lg[e], o);
    __shared__ float gsum[8][Eq];
    if (lane == 0)
#pragma unroll
        for (int e = 0; e < Eq; e++) gsum[warp][e] = lg[e];
    __syncthreads();
    if (threadIdx.x == 0) {
        float tot[Eq];
        float m = -1e30f;
#pragma unroll
        for (int e = 0; e < Eq; e++) {
            float t = bg[e];
#pragma unroll
            for (int w = 0; w < 8; w++) t += gsum[w][e];
            tot[e] = t;
            m = fmaxf(m, t);
        }
        float sum = 0.f;
#pragma unroll
        for (int e = 0; e < Eq; e++) { tot[e] = __expf(tot[e] - m); sum += tot[e]; }
        float is = 1.f / sum;
#pragma unroll
        for (int e = 0; e < Eq; e++) gates[(size_t)row * Eq + e] = tot[e] * is;
    }
}

// ---------------- LN2: sum of pre-weighted bf16 expert outputs ------------------------
__global__ void __launch_bounds__(256)
ln2_kernel(const float* __restrict__ x, const __nv_bfloat16* __restrict__ yb,
           const float* __restrict__ g, const float* __restrict__ be,
           float* __restrict__ out)
{
    const int row = blockIdx.x;
    float v[3];
    float s = 0.f, s2 = 0.f;
#pragma unroll
    for (int i = 0; i < 3; i++) {
        int d = threadIdx.x + i * 256;
        float val = x[(size_t)row * Dq + d];
#pragma unroll
        for (int e = 0; e < Eq; e++)
            val += __bfloat162float(yb[(size_t)e * MPAD * Dq + (size_t)row * Dq + d]);
        v[i] = val;
        s += val; s2 = fmaf(val, val, s2);
    }
    __shared__ float rs[8], rs2[8];
#pragma unroll
    for (int o = 16; o; o >>= 1) { s += __shfl_xor_sync(0xffffffffu, s, o); s2 += __shfl_xor_sync(0xffffffffu, s2, o); }
    const int warp = threadIdx.x >> 5, lane = threadIdx.x & 31;
    if (lane == 0) { rs[warp] = s; rs2[warp] = s2; }
    __syncthreads();
    if (warp == 0) {
        float t  = (lane < 8) ? rs[lane]  : 0.f;
        float t2 = (lane < 8) ? rs2[lane] : 0.f;
#pragma unroll
        for (int o = 4; o; o >>= 1) { t += __shfl_xor_sync(0xffffffffu, t, o); t2 += __shfl_xor_sync(0xffffffffu, t2, o); }
        if (lane == 0) { rs[0] = t; rs2[0] = t2; }
    }
    __syncthreads();
    const float mu  = rs[0] * (1.f / Dq);
    const float var = rs2[0] * (1.f / Dq) - mu * mu;
    const float inv = rsqrtf(var + 1e-5f);
#pragma unroll
    for (int i = 0; i < 3; i++) {
        int d = threadIdx.x + i * 256;
        out[(size_t)row * Dq + d] = (v[i] - mu) * inv * g[d] + be[d];
    }
}

// ====================================================================================
typedef CUresult (*EncFn)(CUtensorMap*, CUtensorMapDataType, cuuint32_t, void*,
                          const cuuint64_t*, const cuuint64_t*, const cuuint32_t*,
                          const cuuint32_t*, CUtensorMapInterleave, CUtensorMapSwizzle,
                          CUtensorMapL2promotion, CUtensorMapFloatOOBfill);

static void make_map(EncFn enc, CUtensorMap* m, void* ptr,
                     uint64_t d0, uint64_t d1, uint64_t d2)
{
    cuuint64_t dims[3] = {d0, d1, d2};
    cuuint64_t strides[2] = {d0 * 2, d0 * d1 * 2};
    cuuint32_t box[3] = {32, 256, 1};
    cuuint32_t es[3] = {1, 1, 1};
    enc(m, CU_TENSOR_MAP_DATA_TYPE_BFLOAT16, 3, ptr, dims, strides, box, es,
        CU_TENSOR_MAP_INTERLEAVE_NONE, CU_TENSOR_MAP_SWIZZLE_64B,
        CU_TENSOR_MAP_L2_PROMOTION_L2_128B, CU_TENSOR_MAP_FLOAT_OOB_FILL_NONE);
}

extern "C" void kernel_launch(void* const* d_in, const int* in_sizes, int n_in,
                              void* d_out, int out_size)
{
    const float* q   = (const float*)d_in[0];
    const float* k   = (const float*)d_in[1];
    const float* v   = (const float*)d_in[2];
    const float* Wq  = (const float*)d_in[3];
    const float* bq  = (const float*)d_in[4];
    const float* Wk  = (const float*)d_in[5];
    const float* bk  = (const float*)d_in[6];
    const float* Wv  = (const float*)d_in[7];
    const float* bv  = (const float*)d_in[8];
    const float* Wo  = (const float*)d_in[9];
    const float* bo  = (const float*)d_in[10];
    const float* ln1g= (const float*)d_in[11];
    const float* ln1b= (const float*)d_in[12];
    const float* ln2g= (const float*)d_in[13];
    const float* ln2b= (const float*)d_in[14];
    const float* Wg  = (const float*)d_in[15];
    const float* bg  = (const float*)d_in[16];
    const float* W1  = (const float*)d_in[17];
    const float* b1  = (const float*)d_in[18];
    const float* W2  = (const float*)d_in[19];
    const float* b2  = (const float*)d_in[20];
    float* out = (float*)d_out;

    float *p_qkvh, *p_tmp, *p_x, *p_gates;
    __nv_bfloat16 *p_inhi, *p_xhi, *p_hhi, *p_yb;
    __nv_bfloat16 *p_w1h, *p_w2h, *p_wqkvo;
    cudaGetSymbolAddress((void**)&p_qkvh, d_qkvh);
    cudaGetSymbolAddress((void**)&p_tmp,  d_tmp);
    cudaGetSymbolAddress((void**)&p_x,    d_x);
    cudaGetSymbolAddress((void**)&p_gates,d_gates);
    cudaGetSymbolAddress((void**)&p_yb,   d_yb);
    cudaGetSymbolAddress((void**)&p_inhi, d_inhi);
    cudaGetSymbolAddress((void**)&p_xhi,  d_xhi);
    cudaGetSymbolAddress((void**)&p_hhi,  d_hhi);
    cudaGetSymbolAddress((void**)&p_w1h,  d_w1t_hi);
    cudaGetSymbolAddress((void**)&p_w2h,  d_w2t_hi);
    cudaGetSymbolAddress((void**)&p_wqkvo, d_wqkvo);

    static EncFn enc = nullptr;
    static cudaStream_t s2 = nullptr;
    static cudaEvent_t evFork = nullptr, evJoin = nullptr;
    if (!enc) {
        void* fp = nullptr;
        cudaDriverEntryPointQueryResult st;
        cudaGetDriverEntryPointByVersion("cuTensorMapEncodeTiled", &fp, 12000,
                                         cudaEnableDefault, &st);
        enc = (EncFn)fp;
        cudaStreamCreateWithFlags(&s2, cudaStreamNonBlocking);
        cudaEventCreateWithFlags(&evFork, cudaEventDisableTiming);
        cudaEventCreateWithFlags(&evJoin, cudaEventDisableTiming);
    }
    CUtensorMap mXh, mHh, mW1h, mW2h;
    make_map(enc, &mXh, p_xhi, Dq, MPAD, 1);
    make_map(enc, &mHh, p_hhi, Fq, MPAD, Eq);
    make_map(enc, &mW1h, p_w1h, Dq, Fq, Eq);
    make_map(enc, &mW2h, p_w2h, Fq, Dq, Eq);

    const dim3 blk(256);
    const dim3 gridQKV(Dq / TN, NTOK / TM, 3);
    const dim3 gridO(Dq / TN, NTOK / TM, 1);
    const dim3 grid1(Fq / 256, MPAD / 256, Eq);
    const dim3 grid2(Dq / 256, MPAD / 256, Eq);
    const int n4 = NTOK * Dq / 4;
    const int sgrid = (n4 + 255) / 256;
    const size_t segQ = (size_t)NTOK * Dq;

    cudaFuncSetAttribute(tc_gemm<2>,  cudaFuncAttributeMaxDynamicSharedMemorySize, TC_SMEM);
    cudaFuncSetAttribute(tc_gemm<3>,  cudaFuncAttributeMaxDynamicSharedMemorySize, TC_SMEM);
    cudaFuncSetAttribute(tc_gemm2<0>, cudaFuncAttributeMaxDynamicSharedMemorySize, TC2_SMEM);
    cudaFuncSetAttribute(tc_gemm2<1>, cudaFuncAttributeMaxDynamicSharedMemorySize, TC2_SMEM);
    cudaFuncSetAttribute(attn_kernel, cudaFuncAttributeMaxDynamicSharedMemorySize, ATT_SMEM);

    __nv_bfloat16* p_qkvshi = p_hhi;   // qkv-hi staging in idle h region

    // --- fork: W1/W2 transposes on s2, joined before GEMM1 ---
    cudaEventRecord(evFork, 0);
    cudaStreamWaitEvent(s2, evFork, 0);
    transpose_split<<<dim3(Dq/64, Fq/32, Eq), blk, 0, s2>>>(W1, p_w1h, Dq, Fq);
    transpose_split<<<dim3(Fq/64, Dq/32, Eq), blk, 0, s2>>>(W2, p_w2h, Fq, Dq);
    cudaEventRecord(evJoin, s2);

    // --- main chain ---
    transpose_qkvo<<<dim3(Dq/64, Dq/32, 4), blk>>>(Wq, Wk, Wv, Wo, p_wqkvo);
    split3_bf16<<<dim3(sgrid, 3), blk>>>(q, k, v, p_qkvshi, n4);
    tc_gemm<2><<<gridQKV, blk, TC_SMEM>>>(p_qkvshi, p_wqkvo,
                                          bq, bk, bv, nullptr, p_qkvh,
                                          NTOK, Dq, Dq, segQ, (size_t)Dq * Dq, segQ);
    attn_kernel<<<dim3(Bq * Hq, 4), blk, ATT_SMEM>>>(p_qkvh, p_qkvh + segQ, p_qkvh + 2 * segQ,
                                                     p_inhi);
    tc_gemm<3><<<gridO, blk, TC_SMEM>>>(p_inhi, p_wqkvo + (size_t)3 * Dq * Dq,
                                        bo, bo, bo, q, p_tmp, NTOK, Dq, Dq, 0, 0, 0);
    ln_gate_kernel<<<NTOK, blk>>>(p_tmp, ln1g, ln1b, Wg, bg, p_x, p_xhi, p_gates);

    // --- join; MoE ---
    cudaStreamWaitEvent(0, evJoin, 0);
    tc_gemm2<0><<<grid1, blk, TC2_SMEM>>>(
        mXh, mW1h, b1, nullptr, p_hhi,
        Fq, Dq, (size_t)Fq, (size_t)MPAD * Fq,
        p_xhi, p_w1h, (size_t)0, (size_t)Fq * Dq);
    tc_gemm2<1><<<grid2, blk, TC2_SMEM>>>(
        mHh, mW2h, b2, p_gates, p_yb,
        Dq, Fq, (size_t)Dq, (size_t)MPAD * Dq,
        p_hhi, p_w2h, (size_t)MPAD * Fq, (size_t)Dq * Fq);

    ln2_kernel<<<NTOK, blk>>>(p_x, p_yb, ln2g, ln2b, out);
}